// round 12
// baseline (speedup 1.0000x reference)
#include <cuda_runtime.h>
#include <math.h>

#define NB   4
#define NTOK 2304
#define DIM  256
#define AGH  512

// ---------------- scratch (device globals; no allocation allowed) ----------------
__device__ float g_Xall[NB*NTOK*512];          // [b][n][c] c=0..255 ir, 256..511 vis
__device__ float g_h1[NB*NTOK*AGH];
__device__ float g_lf[NB*NTOK];
__device__ float g_maskf[NB*NTOK];
__device__ int   g_idx[NB*NTOK];
__device__ int   g_S[NB];
__device__ float g_X[2*NB*NTOK*DIM];           // compacted tokens, slot = mod*NB+b
__device__ float g_xn[2*NB*NTOK*DIM];
__device__ float g_qkv[2*NB*NTOK*3*DIM];
__device__ float g_attn[2*NB*NTOK*DIM];
__device__ float g_x1[2*NB*NTOK*DIM];
__device__ float g_hff[2*NB*NTOK*4*DIM];
__device__ float g_mix[2*NB*NTOK*DIM];

// ---------------- tf32 / bf16 / cp.async helpers --------------------------------
__device__ __forceinline__ unsigned f2tf(float x) {
    unsigned u; asm("cvt.rna.tf32.f32 %0, %1;" : "=r"(u) : "f"(x)); return u;
}
__device__ __forceinline__ unsigned pack_bf16(float lo, float hi) {
    unsigned r; asm("cvt.rn.bf16x2.f32 %0, %1, %2;" : "=r"(r) : "f"(hi), "f"(lo));
    return r;
}
__device__ __forceinline__ void mma8(float (&c)[4], const unsigned (&a)[4],
                                     const unsigned (&b)[2]) {
    asm volatile(
        "mma.sync.aligned.m16n8k8.row.col.f32.tf32.tf32.f32 "
        "{%0,%1,%2,%3}, {%4,%5,%6,%7}, {%8,%9}, {%0,%1,%2,%3};"
        : "+f"(c[0]), "+f"(c[1]), "+f"(c[2]), "+f"(c[3])
        : "r"(a[0]), "r"(a[1]), "r"(a[2]), "r"(a[3]), "r"(b[0]), "r"(b[1]));
}
__device__ __forceinline__ void mma16bf(float (&c)[4], const unsigned (&a)[4],
                                        const unsigned (&b)[2]) {
    asm volatile(
        "mma.sync.aligned.m16n8k16.row.col.f32.bf16.bf16.f32 "
        "{%0,%1,%2,%3}, {%4,%5,%6,%7}, {%8,%9}, {%0,%1,%2,%3};"
        : "+f"(c[0]), "+f"(c[1]), "+f"(c[2]), "+f"(c[3])
        : "r"(a[0]), "r"(a[1]), "r"(a[2]), "r"(a[3]), "r"(b[0]), "r"(b[1]));
}
__device__ __forceinline__ void cpa16(float* dst, const float* src, bool pred) {
    unsigned d = (unsigned)__cvta_generic_to_shared(dst);
    int sz = pred ? 16 : 0;
    asm volatile("cp.async.cg.shared.global [%0], [%1], 16, %2;"
                 :: "r"(d), "l"(src), "r"(sz));
}
#define CP_COMMIT() asm volatile("cp.async.commit_group;" ::: "memory")

// ---------------- prep: transpose to token-major concat + base canvas -----------
__global__ void prep_kernel(const float* __restrict__ f_ir,
                            const float* __restrict__ f_vis,
                            float* __restrict__ out)
{
    __shared__ float ti[32][33], tv[32][33];
    int b = blockIdx.z;
    int c0 = blockIdx.y * 32;
    int n0 = blockIdx.x * 32;
#pragma unroll
    for (int i = 0; i < 4; i++) {
        int c = c0 + threadIdx.y + i * 8;
        size_t off = ((size_t)b*256 + c)*NTOK + n0 + threadIdx.x;
        float vi = f_ir[off], vv = f_vis[off];
        ti[threadIdx.y + i*8][threadIdx.x] = vi;
        tv[threadIdx.y + i*8][threadIdx.x] = vv;
        out[off] = vi + vv;
    }
    __syncthreads();
#pragma unroll
    for (int i = 0; i < 4; i++) {
        int n = n0 + threadIdx.y + i * 8;
        size_t base = ((size_t)b*NTOK + n)*512;
        g_Xall[base + c0 + threadIdx.x]       = ti[threadIdx.x][threadIdx.y + i*8];
        g_Xall[base + 256 + c0 + threadIdx.x] = tv[threadIdx.x][threadIdx.y + i*8];
    }
}

// ---------------- agent tf32 HILO GEMM, cp.async double-buffer (unchanged) ------
template<int ACT, bool RES, bool USE_S, bool HILO>
__global__ void __launch_bounds__(256) tgemm(
                      const float* __restrict__ A,
                      const float* __restrict__ W0, const float* __restrict__ W1,
                      const float* __restrict__ bias0, const float* __restrict__ bias1,
                      const float* __restrict__ R, float* __restrict__ C,
                      int K, int N)
{
    int z = blockIdx.z;
    int b = z & (NB - 1);
    int S = USE_S ? g_S[b] : NTOK;
    int row0 = blockIdx.x * 128;
    if (row0 >= S) return;
    const float* W    = (z < NB) ? W0 : W1;
    const float* bias = (z < NB) ? bias0 : bias1;
    int n0 = blockIdx.y * 64;
    const float* Ab = A + (size_t)z * NTOK * K;
    float*       Cb = C + (size_t)z * NTOK * N;
    const float* Rb = RES ? (R + (size_t)z * NTOK * N) : nullptr;

    extern __shared__ float sh[];                    // 2 x (A 128*36 + W 64*36)
    float* Abuf[2] = { sh,            sh + 192*36 };
    float* Wbuf[2] = { sh + 128*36,   sh + 320*36 };

    int tid  = threadIdx.x;
    int warp = tid >> 5, lane = tid & 31;
    int g = lane >> 2, tig = lane & 3;
    int wm = warp >> 1, wn = warp & 1;

    int ar  = tid >> 3;
    int ac4 = (tid & 7) * 4;

    float acc[2][4][4];
#pragma unroll
    for (int mi = 0; mi < 2; mi++)
#pragma unroll
        for (int ni = 0; ni < 4; ni++)
#pragma unroll
            for (int q = 0; q < 4; q++) acc[mi][ni][q] = 0.f;

    const int NCH = K >> 5;

    auto issue = [&](int c, int bi) {
        int kc = c * 32;
#pragma unroll
        for (int it = 0; it < 4; it++) {
            int r = ar + it * 32;
            int row = row0 + r;
            bool ok = (row < S);
            cpa16(&Abuf[bi][r*36 + ac4], &Ab[(size_t)(ok ? row : 0) * K + kc + ac4], ok);
        }
#pragma unroll
        for (int it = 0; it < 2; it++) {
            int r = ar + it * 32;
            cpa16(&Wbuf[bi][r*36 + ac4], &W[(size_t)(n0 + r) * K + kc + ac4], true);
        }
    };

    issue(0, 0);
    CP_COMMIT();

    for (int c = 0; c < NCH; c++) {
        int cur = c & 1;
        if (c + 1 < NCH) { issue(c + 1, cur ^ 1); CP_COMMIT(); }
        if (c + 1 < NCH) asm volatile("cp.async.wait_group 1;" ::: "memory");
        else             asm volatile("cp.async.wait_group 0;" ::: "memory");
        __syncthreads();

        const float* Asb = Abuf[cur];
        const float* Wsb = Wbuf[cur];
#pragma unroll
        for (int ks = 0; ks < 4; ks++) {
            int base = ks * 8;
            unsigned a_hi[2][4], b_hi[4][2];
            float a_f[2][4], b_f[4][2];
#pragma unroll
            for (int mi = 0; mi < 2; mi++) {
                int rb = wm*32 + mi*16;
                a_f[mi][0] = Asb[(rb + g    )*36 + base + tig];
                a_f[mi][1] = Asb[(rb + 8 + g)*36 + base + tig];
                a_f[mi][2] = Asb[(rb + g    )*36 + base + tig + 4];
                a_f[mi][3] = Asb[(rb + 8 + g)*36 + base + tig + 4];
#pragma unroll
                for (int q = 0; q < 4; q++) a_hi[mi][q] = f2tf(a_f[mi][q]);
            }
#pragma unroll
            for (int ni = 0; ni < 4; ni++) {
                int nb = wn*32 + ni*8;
                b_f[ni][0] = Wsb[(nb + g)*36 + base + tig];
                b_f[ni][1] = Wsb[(nb + g)*36 + base + tig + 4];
                b_hi[ni][0] = f2tf(b_f[ni][0]);
                b_hi[ni][1] = f2tf(b_f[ni][1]);
            }
            if (HILO) {
                unsigned a_lo[2][4], b_lo[4][2];
#pragma unroll
                for (int mi = 0; mi < 2; mi++)
#pragma unroll
                    for (int q = 0; q < 4; q++)
                        a_lo[mi][q] = f2tf(a_f[mi][q] - __uint_as_float(a_hi[mi][q]));
#pragma unroll
                for (int ni = 0; ni < 4; ni++) {
                    b_lo[ni][0] = f2tf(b_f[ni][0] - __uint_as_float(b_hi[ni][0]));
                    b_lo[ni][1] = f2tf(b_f[ni][1] - __uint_as_float(b_hi[ni][1]));
                }
#pragma unroll
                for (int mi = 0; mi < 2; mi++)
#pragma unroll
                    for (int ni = 0; ni < 4; ni++) {
                        mma8(acc[mi][ni], a_hi[mi], b_lo[ni]);
                        mma8(acc[mi][ni], a_lo[mi], b_hi[ni]);
                        mma8(acc[mi][ni], a_hi[mi], b_hi[ni]);
                    }
            } else {
#pragma unroll
                for (int mi = 0; mi < 2; mi++)
#pragma unroll
                    for (int ni = 0; ni < 4; ni++)
                        mma8(acc[mi][ni], a_hi[mi], b_hi[ni]);
            }
        }
        __syncthreads();
    }

#pragma unroll
    for (int mi = 0; mi < 2; mi++) {
#pragma unroll
        for (int ni = 0; ni < 4; ni++) {
            int cb = n0 + wn*32 + ni*8 + 2*tig;
            float2 bb = *(const float2*)&bias[cb];
#pragma unroll
            for (int h = 0; h < 2; h++) {
                int row = row0 + wm*32 + mi*16 + g + h*8;
                if (row >= S) continue;
                float v0 = acc[mi][ni][h*2 + 0] + bb.x;
                float v1 = acc[mi][ni][h*2 + 1] + bb.y;
                if (ACT == 1) {
                    v0 = 0.5f * v0 * (1.f + erff(v0 * 0.70710678118654752f));
                    v1 = 0.5f * v1 * (1.f + erff(v1 * 0.70710678118654752f));
                } else if (ACT == 2) {
                    v0 = v0 / (1.f + expf(-v0));
                    v1 = v1 / (1.f + expf(-v1));
                }
                if (RES) {
                    float2 rr = *(const float2*)&Rb[(size_t)row * N + cb];
                    v0 += rr.x; v1 += rr.y;
                }
                *(float2*)&Cb[(size_t)row * N + cb] = make_float2(v0, v1);
            }
        }
    }
}

// ---------------- mixer bf16 GEMM: mma.m16n8k16, K-chunk 64 (fewer barriers) ----
// block tile 128(M) x 64(N), K-chunk 64 floats = 32 bf16x2 pairs, 8 warps.
// smem row stride 36 uints (0 mod 4 -> uint4-aligned; 36g mod 32 distinct -> no conflicts)
template<int ACT, bool RES>
__global__ void __launch_bounds__(256) bgemm(
                      const float* __restrict__ A,
                      const float* __restrict__ W0, const float* __restrict__ W1,
                      const float* __restrict__ bias0, const float* __restrict__ bias1,
                      const float* __restrict__ R, float* __restrict__ C,
                      int K, int N)
{
    int z = blockIdx.z;
    int b = z & (NB - 1);
    int S = g_S[b];
    int row0 = blockIdx.x * 128;
    if (row0 >= S) return;
    const float* W    = (z < NB) ? W0 : W1;
    const float* bias = (z < NB) ? bias0 : bias1;
    int n0 = blockIdx.y * 64;
    const float* Ab = A + (size_t)z * NTOK * K;
    float*       Cb = C + (size_t)z * NTOK * N;
    const float* Rb = RES ? (R + (size_t)z * NTOK * N) : nullptr;

    __shared__ unsigned As[128*36];
    __shared__ unsigned Ws[64*36];

    int tid  = threadIdx.x;
    int warp = tid >> 5, lane = tid & 31;
    int g = lane >> 2, tig = lane & 3;
    int wm = warp >> 1, wn = warp & 1;

    // A staging: 2 threads/row, each half = 32 floats (8 float4 -> 16 pairs)
    int arow = tid >> 1;
    int ahalf = (tid & 1) * 32;
    // W staging: 4 threads/row, each quarter = 16 floats (4 float4 -> 8 pairs)
    int wrow = tid >> 2;
    int wquart = (tid & 3) * 16;

    float acc[2][4][4];
#pragma unroll
    for (int mi = 0; mi < 2; mi++)
#pragma unroll
        for (int ni = 0; ni < 4; ni++)
#pragma unroll
            for (int q = 0; q < 4; q++) acc[mi][ni][q] = 0.f;

    for (int k0 = 0; k0 < K; k0 += 64) {
        // stage A: 128 rows x 64 floats -> bf16 pairs
        {
            int row = row0 + arow;
            float4 v[8];
#pragma unroll
            for (int i = 0; i < 8; i++) v[i] = make_float4(0.f,0.f,0.f,0.f);
            if (row < S) {
                const float* p = &Ab[(size_t)row * K + k0 + ahalf];
#pragma unroll
                for (int i = 0; i < 8; i++) v[i] = *(const float4*)(p + 4*i);
            }
#pragma unroll
            for (int i = 0; i < 2; i++) {
                uint4 u;
                u.x = pack_bf16(v[4*i+0].x, v[4*i+0].y); u.y = pack_bf16(v[4*i+0].z, v[4*i+0].w);
                u.z = pack_bf16(v[4*i+1].x, v[4*i+1].y); u.w = pack_bf16(v[4*i+1].z, v[4*i+1].w);
                uint4 u2;
                u2.x = pack_bf16(v[4*i+2].x, v[4*i+2].y); u2.y = pack_bf16(v[4*i+2].z, v[4*i+2].w);
                u2.z = pack_bf16(v[4*i+3].x, v[4*i+3].y); u2.w = pack_bf16(v[4*i+3].z, v[4*i+3].w);
                *(uint4*)&As[arow*36 + (ahalf >> 1) + 8*i]     = u;
                *(uint4*)&As[arow*36 + (ahalf >> 1) + 8*i + 4] = u2;
            }
        }
        // stage W: 64 rows x 64 floats
        {
            const float* p = &W[(size_t)(n0 + wrow) * K + k0 + wquart];
            float4 v0 = *(const float4*)(p);
            float4 v1 = *(const float4*)(p + 4);
            float4 v2 = *(const float4*)(p + 8);
            float4 v3 = *(const float4*)(p + 12);
            uint4 u;
            u.x = pack_bf16(v0.x, v0.y); u.y = pack_bf16(v0.z, v0.w);
            u.z = pack_bf16(v1.x, v1.y); u.w = pack_bf16(v1.z, v1.w);
            uint4 u2;
            u2.x = pack_bf16(v2.x, v2.y); u2.y = pack_bf16(v2.z, v2.w);
            u2.z = pack_bf16(v3.x, v3.y); u2.w = pack_bf16(v3.z, v3.w);
            *(uint4*)&Ws[wrow*36 + (wquart >> 1)]     = u;
            *(uint4*)&Ws[wrow*36 + (wquart >> 1) + 4] = u2;
        }
        __syncthreads();

#pragma unroll
        for (int ks = 0; ks < 4; ks++) {        // each ks covers k=16 (8 pairs)
            int base = ks * 8;
            unsigned a[2][4], bf[4][2];
#pragma unroll
            for (int mi = 0; mi < 2; mi++) {
                int rb = wm*32 + mi*16;
                a[mi][0] = As[(rb + g    )*36 + base + tig];
                a[mi][1] = As[(rb + 8 + g)*36 + base + tig];
                a[mi][2] = As[(rb + g    )*36 + base + tig + 4];
                a[mi][3] = As[(rb + 8 + g)*36 + base + tig + 4];
            }
#pragma unroll
            for (int ni = 0; ni < 4; ni++) {
                int nb = wn*32 + ni*8;
                bf[ni][0] = Ws[(nb + g)*36 + base + tig];
                bf[ni][1] = Ws[(nb + g)*36 + base + tig + 4];
            }
#pragma unroll
            for (int mi = 0; mi < 2; mi++)
#pragma unroll
                for (int ni = 0; ni < 4; ni++)
                    mma16bf(acc[mi][ni], a[mi], bf[ni]);
        }
        __syncthreads();
    }

    // epilogue
#pragma unroll
    for (int mi = 0; mi < 2; mi++) {
#pragma unroll
        for (int ni = 0; ni < 4; ni++) {
            int cb = n0 + wn*32 + ni*8 + 2*tig;
            float2 bb = *(const float2*)&bias[cb];
#pragma unroll
            for (int h = 0; h < 2; h++) {
                int row = row0 + wm*32 + mi*16 + g + h*8;
                if (row >= S) continue;
                float v0 = acc[mi][ni][h*2 + 0] + bb.x;
                float v1 = acc[mi][ni][h*2 + 1] + bb.y;
                if (ACT == 1) {
                    v0 = 0.5f * v0 * (1.f + erff(v0 * 0.70710678118654752f));
                    v1 = 0.5f * v1 * (1.f + erff(v1 * 0.70710678118654752f));
                }
                if (RES) {
                    float2 rr = *(const float2*)&Rb[(size_t)row * N + cb];
                    v0 += rr.x; v1 += rr.y;
                }
                *(float2*)&Cb[(size_t)row * N + cb] = make_float2(v0, v1);
            }
        }
    }
}

// ---------------- logits: lf[p] = h1[p]·aw2 + ab2 (warp per pixel) --------------
__global__ void logits_kernel(const float* __restrict__ aw2,
                              const float* __restrict__ ab2)
{
    int p = blockIdx.x * 8 + (threadIdx.x >> 5);
    int lane = threadIdx.x & 31;
    const float* h = g_h1 + (size_t)p * AGH;
    float s = 0.f;
#pragma unroll
    for (int j = 0; j < 16; j++) s += h[lane + 32*j] * aw2[lane + 32*j];
#pragma unroll
    for (int o = 16; o > 0; o >>= 1) s += __shfl_xor_sync(0xffffffffu, s, o);
    if (lane == 0) g_lf[p] = s + ab2[0];
}

// ---------------- selection + top-64 fallback + compaction ----------------------
__global__ void select_kernel()
{
    __shared__ float vals[NTOK];
    __shared__ int   sels[NTOK];
    __shared__ int   wtot[8];
    __shared__ int   scount;
    __shared__ float rv[256];
    __shared__ int   ri[256];
    int b = blockIdx.x, tid = threadIdx.x;
    int lane = tid & 31, w = tid >> 5;

    int localc = 0;
    for (int n = tid; n < NTOK; n += 256) {
        float v = g_lf[b*NTOK + n];
        vals[n] = v;
        int s = (v > 0.f) ? 1 : 0;
        sels[n] = s;
        g_maskf[b*NTOK + n] = s ? 1.f : 0.f;
        localc += s;
    }
    {
        int c = localc;
#pragma unroll
        for (int o = 16; o > 0; o >>= 1) c += __shfl_xor_sync(0xffffffffu, c, o);
        if (lane == 0) wtot[w] = c;
        __syncthreads();
        if (tid == 0) { int t = 0; for (int i = 0; i < 8; i++) t += wtot[i]; scount = t; }
        __syncthreads();
    }
    int count = scount;

    if (count < 64) {
        for (int n = tid; n < NTOK; n += 256) sels[n] = 0;
        __syncthreads();
        for (int iter = 0; iter < 64; iter++) {
            float bv = -1e38f; int bi = NTOK;
            for (int n = tid; n < NTOK; n += 256)
                if (!sels[n] && vals[n] > bv) { bv = vals[n]; bi = n; }
            rv[tid] = bv; ri[tid] = bi;
            __syncthreads();
            for (int o = 128; o > 0; o >>= 1) {
                if (tid < o) {
                    if (rv[tid+o] > rv[tid] ||
                        (rv[tid+o] == rv[tid] && ri[tid+o] < ri[tid])) {
                        rv[tid] = rv[tid+o]; ri[tid] = ri[tid+o];
                    }
                }
                __syncthreads();
            }
            if (tid == 0) sels[ri[0]] = 1;
            __syncthreads();
        }
    }

    int base = tid * 9;
    int lc = 0;
#pragma unroll
    for (int k = 0; k < 9; k++) lc += sels[base + k];
    int inc = lc;
#pragma unroll
    for (int o = 1; o < 32; o <<= 1) {
        int v = __shfl_up_sync(0xffffffffu, inc, o);
        if (lane >= o) inc += v;
    }
    if (lane == 31) wtot[w] = inc;
    __syncthreads();
    if (tid < 8) {
        int v = wtot[tid];
#pragma unroll
        for (int o = 1; o < 8; o <<= 1) {
            int u = __shfl_up_sync(0xffu, v, o);
            if (tid >= o) v += u;
        }
        wtot[tid] = v;
    }
    __syncthreads();
    int pos = inc - lc + (w ? wtot[w-1] : 0);
    if (tid == 0) g_S[b] = wtot[7];
#pragma unroll
    for (int k = 0; k < 9; k++)
        if (sels[base + k]) g_idx[b*NTOK + pos++] = base + k;
}

// ---------------- gather compacted tokens (both modules) ------------------------
__global__ void gather_kernel()
{
    int b = blockIdx.y, s = blockIdx.x;
    if (s >= g_S[b]) return;
    int n = g_idx[b*NTOK + s];
    int c = threadIdx.x;
    const float* src = g_Xall + ((size_t)b*NTOK + n)*512;
    g_X[((size_t)b*NTOK + s)*DIM + c]        = src[c];
    g_X[((size_t)(NB + b)*NTOK + s)*DIM + c] = src[256 + c];
}

// ---------------- LayerNorm (warp per token) ------------------------------------
__global__ void ln_kernel(const float* __restrict__ X,
                          const float* __restrict__ g0, const float* __restrict__ b0_,
                          const float* __restrict__ g1, const float* __restrict__ b1_,
                          float* __restrict__ O)
{
    int z = blockIdx.y;
    int b = z & (NB - 1);
    int t = blockIdx.x * 8 + (threadIdx.x >> 5);
    if (t >= g_S[b]) return;
    const float* gg = (z < NB) ? g0 : g1;
    const float* bb = (z < NB) ? b0_ : b1_;
    int lane = threadIdx.x & 31;
    const float* x = X + ((size_t)z*NTOK + t)*DIM;
    float v[8];
    float s = 0.f;
#pragma unroll
    for (int j = 0; j < 8; j++) { v[j] = x[lane + 32*j]; s += v[j]; }
#pragma unroll
    for (int o = 16; o > 0; o >>= 1) s += __shfl_xor_sync(0xffffffffu, s, o);
    float mean = s * (1.f/256.f);
    float vs = 0.f;
#pragma unroll
    for (int j = 0; j < 8; j++) { float d = v[j] - mean; vs += d*d; }
#pragma unroll
    for (int o = 16; o > 0; o >>= 1) vs += __shfl_xor_sync(0xffffffffu, vs, o);
    float rstd = rsqrtf(vs * (1.f/256.f) + 1e-5f);
    float* o = O + ((size_t)z*NTOK + t)*DIM;
#pragma unroll
    for (int j = 0; j < 8; j++) {
        int c = lane + 32*j;
        o[c] = (v[j] - mean) * rstd * gg[c] + bb[c];
    }
}

// ---------------- flash attention, tf32 mma, scalar LDS (dh=64, 4 heads) --------
__global__ void flash_kernel()
{
    extern __shared__ unsigned fsm[];
    unsigned* Qs  = fsm;                 // [q][d] tf32, stride 68
    unsigned* Ks  = fsm + 64*68;         // [k][d] tf32
    unsigned* Vst = fsm + 2*64*68;       // [d][key] tf32 (transposed)
    float*    Ss  = (float*)(fsm + 3*64*68);   // [q][k] scores / p(tf32)
    unsigned* Psu = fsm + 3*64*68;
    __shared__ float m_s[64], l_s[64], al_s[64];

    int z = blockIdx.z;
    int b = z & (NB - 1);
    int h = blockIdx.y;
    int S = g_S[b];
    int qb = blockIdx.x * 64;
    if (qb >= S) return;
    int tid = threadIdx.x;
    int warp = tid >> 5, lane = tid & 31;
    int g = lane >> 2, tig = lane & 3;
    int wm = warp >> 1, wn = warp & 1;
    const float* qkvb = g_qkv + (size_t)z * NTOK * 768;

#pragma unroll
    for (int it = 0; it < 4; it++) {
        int lin = tid + it * 256;
        int r = lin >> 4, c4 = (lin & 15) * 4;
        int t = qb + r;
        float4 v = make_float4(0.f, 0.f, 0.f, 0.f);
        if (t < S) v = *(const float4*)&qkvb[(size_t)t*768 + h*64 + c4];
        uint4 hv; hv.x = f2tf(v.x); hv.y = f2tf(v.y); hv.z = f2tf(v.z); hv.w = f2tf(v.w);
        *(uint4*)&Qs[r*68 + c4] = hv;
    }
    if (tid < 64) { m_s[tid] = -1e30f; l_s[tid] = 0.f; }

    float oacc[4][4];
#pragma unroll
    for (int ni = 0; ni < 4; ni++)
#pragma unroll
        for (int q = 0; q < 4; q++) oacc[ni][q] = 0.f;

    for (int kb = 0; kb < S; kb += 64) {
        __syncthreads();
#pragma unroll
        for (int it = 0; it < 4; it++) {
            int lin = tid + it * 256;
            int r = lin >> 4, c4 = (lin & 15) * 4;
            int t = kb + r;
            float4 v = make_float4(0.f, 0.f, 0.f, 0.f);
            if (t < S) v = *(const float4*)&qkvb[(size_t)t*768 + 256 + h*64 + c4];
            uint4 hv; hv.x = f2tf(v.x); hv.y = f2tf(v.y); hv.z = f2tf(v.z); hv.w = f2tf(v.w);
            *(uint4*)&Ks[r*68 + c4] = hv;
        }
#pragma unroll
        for (int it = 0; it < 16; it++) {
            int lin = tid + it * 256;
            int d = lin & 63, tt = lin >> 6;
            int t = kb + tt;
            float v = (t < S) ? qkvb[(size_t)t*768 + 512 + h*64 + d] : 0.f;
            Vst[d*68 + tt] = f2tf(v);
        }
        __syncthreads();

        float sacc[4][4];
#pragma unroll
        for (int ni = 0; ni < 4; ni++)
#pragma unroll
            for (int q = 0; q < 4; q++) sacc[ni][q] = 0.f;
#pragma unroll
        for (int ks = 0; ks < 8; ks++) {
            int base = ks * 8;
            unsigned a[4];
            int rb = wm * 16;
            a[0] = Qs[(rb + g    )*68 + base + tig];
            a[1] = Qs[(rb + 8 + g)*68 + base + tig];
            a[2] = Qs[(rb + g    )*68 + base + tig + 4];
            a[3] = Qs[(rb + 8 + g)*68 + base + tig + 4];
#pragma unroll
            for (int ni = 0; ni < 4; ni++) {
                int key = wn*32 + ni*8 + g;
                unsigned bf[2];
                bf[0] = Ks[key*68 + base + tig];
                bf[1] = Ks[key*68 + base + tig + 4];
                mma8(sacc[ni], a, bf);
            }
        }
#pragma unroll
        for (int ni = 0; ni < 4; ni++) {
            int kcol = wn*32 + ni*8 + 2*tig;
            int q0 = wm*16 + g;
            float s0 = sacc[ni][0] * 0.125f, s1 = sacc[ni][1] * 0.125f;
            float s2 = sacc[ni][2] * 0.125f, s3 = sacc[ni][3] * 0.125f;
            if (kb + kcol     >= S) { s0 = -1e30f; s2 = -1e30f; }
            if (kb + kcol + 1 >= S) { s1 = -1e30f; s3 = -1e30f; }
            *(float2*)&Ss[q0*68 + kcol]     = make_float2(s0, s1);
            *(float2*)&Ss[(q0+8)*68 + kcol] = make_float2(s2, s3);
        }
        __syncthreads();

        {
            int row = tid >> 2, sub = tid & 3;
            float* Sr = Ss + row*68;
            float vv[16];
            float rm = -1e30f;
#pragma unroll
            for (int j = 0; j < 16; j++) { vv[j] = Sr[sub + 4*j]; rm = fmaxf(rm, vv[j]); }
            rm = fmaxf(rm, __shfl_xor_sync(0xffffffffu, rm, 1));
            rm = fmaxf(rm, __shfl_xor_sync(0xffffffffu, rm, 2));
            float mo = m_s[row];
            float mn = fmaxf(mo, rm);
            float rs = 0.f;
#pragma unroll
            for (int j = 0; j < 16; j++) {
                float p = __expf(vv[j] - mn);
                rs += p;
                Sr[sub + 4*j] = __uint_as_float(f2tf(p));
            }
            rs += __shfl_xor_sync(0xffffffffu, rs, 1);
            rs += __shfl_xor_sync(0xffffffffu, rs, 2);
            if (sub == 0) {
                float al = __expf(mo - mn);
                l_s[row] = l_s[row] * al + rs;
                m_s[row] = mn;
                al_s[row] = al;
            }
        }
        __syncthreads();

        {
            float al0 = al_s[wm*16 + g];
            float al1 = al_s[wm*16 + 8 + g];
#pragma unroll
            for (int ni = 0; ni < 4; ni++) {
                oacc[ni][0] *= al0; oacc[ni][1] *= al0;
                oacc[ni][2] *= al1; oacc[ni][3] *= al1;
            }
        }

#pragma unroll
        for (int ks = 0; ks < 8; ks++) {
            int base = ks * 8;
            unsigned a[4];
            int rb = wm * 16;
            a[0] = Psu[(rb + g    )*68 + base + tig];
            a[1] = Psu[(rb + 8 + g)*68 + base + tig];
            a[2] = Psu[(rb + g    )*68 + base + tig + 4];
            a[3] = Psu[(rb + 8 + g)*68 + base + tig + 4];
#pragma unroll
            for (int ni = 0; ni < 4; ni++) {
                int d = wn*32 + ni*8 + g;
                unsigned bf[2];
                bf[0] = Vst[d*68 + base + tig];
                bf[1] = Vst[d*68 + base + tig + 4];
                mma8(oacc[ni], a, bf);
            }
        }
    }

    {
        int q0 = wm*16 + g;
        float il0 = 1.f / l_s[q0];
        float il1 = 1.f / l_s[q0 + 8];
        int t0 = qb + q0, t1 = qb + q0 + 8;
        float* ab = g_attn + (size_t)z * NTOK * DIM;
#pragma unroll
        for (int ni = 0; ni < 4; ni++) {
            int d = h*64 + wn*32 + ni*8 + 2*tig;
            if (t0 < S)
                *(float2*)&ab[(size_t)t0*DIM + d] = make_float2(oacc[ni][0]*il0, oacc[ni][1]*il0);
            if (t1 < S)
                *(float2*)&ab[(size_t)t1*DIM + d] = make_float2(oacc[ni][2]*il1, oacc[ni][3]*il1);
        }
    }
}

// ---------------- final scatter -------------------------------------------------
__global__ void scatter_kernel(float* __restrict__ out)
{
    int b = blockIdx.y, s = blockIdx.x;
    if (s >= g_S[b]) return;
    int n = g_idx[b*NTOK + s];
    int c = threadIdx.x;
    float v = (g_mix[((size_t)b*NTOK + s)*DIM + c] +
               g_mix[((size_t)(NB + b)*NTOK + s)*DIM + c]) * g_maskf[b*NTOK + n];
    out[((size_t)b*DIM + c)*NTOK + n] = v;
}

// ---------------- host ----------------------------------------------------------
#define GETSYM(ptr, sym) cudaGetSymbolAddress((void**)&(ptr), sym)

extern "C" void kernel_launch(void* const* d_in, const int* in_sizes, int n_in,
                              void* d_out, int out_size)
{
    const float* f_ir  = (const float*)d_in[0];
    const float* f_vis = (const float*)d_in[1];
    const float* aw1   = (const float*)d_in[2];
    const float* ab1   = (const float*)d_in[3];
    const float* aw2   = (const float*)d_in[4];
    const float* ab2   = (const float*)d_in[5];
    const float* P[20];
    for (int i = 0; i < 20; i++) P[i] = (const float*)d_in[6 + i];
    float* out = (float*)d_out;

    float *p_Xall, *p_h1, *p_X, *p_xn, *p_qkv, *p_attn, *p_x1, *p_hff, *p_mix;
    GETSYM(p_Xall, g_Xall); GETSYM(p_h1, g_h1); GETSYM(p_X, g_X);
    GETSYM(p_xn, g_xn);     GETSYM(p_qkv, g_qkv); GETSYM(p_attn, g_attn);
    GETSYM(p_x1, g_x1);     GETSYM(p_hff, g_hff); GETSYM(p_mix, g_mix);

    const int SMG = 2*192*36*4;    // 55296 B : agent double-buffered fp32 tiles
    const int SMF = 4*64*68*4;     // 69632 B : flash

    cudaFuncSetAttribute(tgemm<2,false,false,true>, cudaFuncAttributeMaxDynamicSharedMemorySize, SMG);
    cudaFuncSetAttribute(flash_kernel, cudaFuncAttributeMaxDynamicSharedMemorySize, SMF);

    prep_kernel<<<dim3(72, 8, NB), dim3(32, 8)>>>(f_ir, f_vis, out);
    // agent: 3xTF32 (fp32-grade; logit sign decisions are razor-thin), silu
    tgemm<2,false,false,true><<<dim3(18, 8, NB), 256, SMG>>>(
        p_Xall, aw1, aw1, ab1, ab1, nullptr, p_h1, 512, 512);
    logits_kernel<<<1152, 256>>>(aw2, ab2);
    select_kernel<<<NB, 256>>>();
    gather_kernel<<<dim3(NTOK, NB), 256>>>();

    // fused ir+vis mixer pipeline (bf16 tensor cores, K-chunk 64): z = mod*NB + b
    ln_kernel<<<dim3(288, 8), 256>>>(p_X, P[0], P[1], P[10], P[11], p_xn);
    bgemm<0,false><<<dim3(18, 12, 8), 256>>>(
        p_xn, P[2], P[12], P[3], P[13], nullptr, p_qkv, 256, 768);
    flash_kernel<<<dim3(36, 4, 8), 256, SMF>>>();
    bgemm<0,true><<<dim3(18, 4, 8), 256>>>(
        p_attn, P[4], P[14], P[5], P[15], p_X, p_x1, 256, 256);
    ln_kernel<<<dim3(288, 8), 256>>>(p_x1, P[0], P[1], P[10], P[11], p_xn);
    bgemm<1,false><<<dim3(18, 16, 8), 256>>>(
        p_xn, P[6], P[16], P[7], P[17], nullptr, p_hff, 256, 1024);
    bgemm<0,true><<<dim3(18, 4, 8), 256>>>(
        p_hff, P[8], P[18], P[9], P[19], p_x1, p_mix, 1024, 256);

    scatter_kernel<<<dim3(NTOK, NB), 256>>>(out);
}

// round 13
// speedup vs baseline: 1.0459x; 1.0459x over previous
#include <cuda_runtime.h>
#include <math.h>

#define NB   4
#define NTOK 2304
#define DIM  256
#define AGH  512

// ---------------- scratch (device globals; no allocation allowed) ----------------
__device__ float g_Xall[NB*NTOK*512];          // [b][n][c] c=0..255 ir, 256..511 vis
__device__ float g_h1[NB*NTOK*AGH];
__device__ float g_lf[NB*NTOK];
__device__ float g_maskf[NB*NTOK];
__device__ int   g_idx[NB*NTOK];
__device__ int   g_S[NB];
__device__ float g_X[2*NB*NTOK*DIM];           // compacted tokens, slot = mod*NB+b
__device__ float g_xn[2*NB*NTOK*DIM];
__device__ float g_qkv[2*NB*NTOK*3*DIM];
__device__ float g_attn[2*NB*NTOK*DIM];
__device__ float g_x1[2*NB*NTOK*DIM];
__device__ float g_hff[2*NB*NTOK*4*DIM];
__device__ float g_mix[2*NB*NTOK*DIM];

// ---------------- tf32 / bf16 / cp.async helpers --------------------------------
__device__ __forceinline__ unsigned f2tf(float x) {
    unsigned u; asm("cvt.rna.tf32.f32 %0, %1;" : "=r"(u) : "f"(x)); return u;
}
__device__ __forceinline__ unsigned pack_bf16(float lo, float hi) {
    unsigned r; asm("cvt.rn.bf16x2.f32 %0, %1, %2;" : "=r"(r) : "f"(hi), "f"(lo));
    return r;
}
__device__ __forceinline__ void mma8(float (&c)[4], const unsigned (&a)[4],
                                     const unsigned (&b)[2]) {
    asm volatile(
        "mma.sync.aligned.m16n8k8.row.col.f32.tf32.tf32.f32 "
        "{%0,%1,%2,%3}, {%4,%5,%6,%7}, {%8,%9}, {%0,%1,%2,%3};"
        : "+f"(c[0]), "+f"(c[1]), "+f"(c[2]), "+f"(c[3])
        : "r"(a[0]), "r"(a[1]), "r"(a[2]), "r"(a[3]), "r"(b[0]), "r"(b[1]));
}
__device__ __forceinline__ void mma16bf(float (&c)[4], const unsigned (&a)[4],
                                        const unsigned (&b)[2]) {
    asm volatile(
        "mma.sync.aligned.m16n8k16.row.col.f32.bf16.bf16.f32 "
        "{%0,%1,%2,%3}, {%4,%5,%6,%7}, {%8,%9}, {%0,%1,%2,%3};"
        : "+f"(c[0]), "+f"(c[1]), "+f"(c[2]), "+f"(c[3])
        : "r"(a[0]), "r"(a[1]), "r"(a[2]), "r"(a[3]), "r"(b[0]), "r"(b[1]));
}
__device__ __forceinline__ void cpa16(float* dst, const float* src, bool pred) {
    unsigned d = (unsigned)__cvta_generic_to_shared(dst);
    int sz = pred ? 16 : 0;
    asm volatile("cp.async.cg.shared.global [%0], [%1], 16, %2;"
                 :: "r"(d), "l"(src), "r"(sz));
}
#define CP_COMMIT() asm volatile("cp.async.commit_group;" ::: "memory")

// ---------------- prep: transpose to token-major concat + base canvas -----------
__global__ void prep_kernel(const float* __restrict__ f_ir,
                            const float* __restrict__ f_vis,
                            float* __restrict__ out)
{
    __shared__ float ti[32][33], tv[32][33];
    int b = blockIdx.z;
    int c0 = blockIdx.y * 32;
    int n0 = blockIdx.x * 32;
#pragma unroll
    for (int i = 0; i < 4; i++) {
        int c = c0 + threadIdx.y + i * 8;
        size_t off = ((size_t)b*256 + c)*NTOK + n0 + threadIdx.x;
        float vi = f_ir[off], vv = f_vis[off];
        ti[threadIdx.y + i*8][threadIdx.x] = vi;
        tv[threadIdx.y + i*8][threadIdx.x] = vv;
        out[off] = vi + vv;
    }
    __syncthreads();
#pragma unroll
    for (int i = 0; i < 4; i++) {
        int n = n0 + threadIdx.y + i * 8;
        size_t base = ((size_t)b*NTOK + n)*512;
        g_Xall[base + c0 + threadIdx.x]       = ti[threadIdx.x][threadIdx.y + i*8];
        g_Xall[base + 256 + c0 + threadIdx.x] = tv[threadIdx.x][threadIdx.y + i*8];
    }
}

// ---------------- unified GEMM, cp.async double-buffer ---------------------------
// block tile 128(M) x 64(N), K-chunk 32, 8 warps (4M x 2N), warp tile 32x32.
// smem holds raw fp32; fragments built at load:
//   BF16=false: cvt.rna.tf32 (+ optional HILO 3xTF32, fp32-grade — agent path)
//   BF16=true : float2 -> cvt.rn.bf16x2 pack, mma.m16n8k16 (mixer path, 2x rate)
template<int ACT, bool RES, bool USE_S, bool HILO, bool BF16>
__global__ void __launch_bounds__(256) tgemm(
                      const float* __restrict__ A,
                      const float* __restrict__ W0, const float* __restrict__ W1,
                      const float* __restrict__ bias0, const float* __restrict__ bias1,
                      const float* __restrict__ R, float* __restrict__ C,
                      int K, int N)
{
    int z = blockIdx.z;
    int b = z & (NB - 1);
    int S = USE_S ? g_S[b] : NTOK;
    int row0 = blockIdx.x * 128;
    if (row0 >= S) return;
    const float* W    = (z < NB) ? W0 : W1;
    const float* bias = (z < NB) ? bias0 : bias1;
    int n0 = blockIdx.y * 64;
    const float* Ab = A + (size_t)z * NTOK * K;
    float*       Cb = C + (size_t)z * NTOK * N;
    const float* Rb = RES ? (R + (size_t)z * NTOK * N) : nullptr;

    extern __shared__ float sh[];                    // 2 x (A 128*36 + W 64*36)
    float* Abuf[2] = { sh,            sh + 192*36 };
    float* Wbuf[2] = { sh + 128*36,   sh + 320*36 };

    int tid  = threadIdx.x;
    int warp = tid >> 5, lane = tid & 31;
    int g = lane >> 2, tig = lane & 3;
    int wm = warp >> 1, wn = warp & 1;

    int ar  = tid >> 3;
    int ac4 = (tid & 7) * 4;

    float acc[2][4][4];
#pragma unroll
    for (int mi = 0; mi < 2; mi++)
#pragma unroll
        for (int ni = 0; ni < 4; ni++)
#pragma unroll
            for (int q = 0; q < 4; q++) acc[mi][ni][q] = 0.f;

    const int NCH = K >> 5;

    auto issue = [&](int c, int bi) {
        int kc = c * 32;
#pragma unroll
        for (int it = 0; it < 4; it++) {
            int r = ar + it * 32;
            int row = row0 + r;
            bool ok = (row < S);
            cpa16(&Abuf[bi][r*36 + ac4], &Ab[(size_t)(ok ? row : 0) * K + kc + ac4], ok);
        }
#pragma unroll
        for (int it = 0; it < 2; it++) {
            int r = ar + it * 32;
            cpa16(&Wbuf[bi][r*36 + ac4], &W[(size_t)(n0 + r) * K + kc + ac4], true);
        }
    };

    issue(0, 0);
    CP_COMMIT();

    for (int c = 0; c < NCH; c++) {
        int cur = c & 1;
        if (c + 1 < NCH) { issue(c + 1, cur ^ 1); CP_COMMIT(); }
        if (c + 1 < NCH) asm volatile("cp.async.wait_group 1;" ::: "memory");
        else             asm volatile("cp.async.wait_group 0;" ::: "memory");
        __syncthreads();

        const float* Asb = Abuf[cur];
        const float* Wsb = Wbuf[cur];

        if (BF16) {
            // two k16 slabs per 32-chunk, mma.m16n8k16.bf16
#pragma unroll
            for (int ks2 = 0; ks2 < 2; ks2++) {
                int base = ks2 * 16;
                unsigned a[2][4], bf[4][2];
#pragma unroll
                for (int mi = 0; mi < 2; mi++) {
                    int rb = wm*32 + mi*16;
                    const float* r0 = &Asb[(rb + g    )*36 + base];
                    const float* r1 = &Asb[(rb + 8 + g)*36 + base];
                    a[mi][0] = pack_bf16(r0[2*tig],     r0[2*tig + 1]);
                    a[mi][1] = pack_bf16(r1[2*tig],     r1[2*tig + 1]);
                    a[mi][2] = pack_bf16(r0[8 + 2*tig], r0[8 + 2*tig + 1]);
                    a[mi][3] = pack_bf16(r1[8 + 2*tig], r1[8 + 2*tig + 1]);
                }
#pragma unroll
                for (int ni = 0; ni < 4; ni++) {
                    int nb = wn*32 + ni*8;
                    const float* rw = &Wsb[(nb + g)*36 + base];
                    bf[ni][0] = pack_bf16(rw[2*tig],     rw[2*tig + 1]);
                    bf[ni][1] = pack_bf16(rw[8 + 2*tig], rw[8 + 2*tig + 1]);
                }
#pragma unroll
                for (int mi = 0; mi < 2; mi++)
#pragma unroll
                    for (int ni = 0; ni < 4; ni++)
                        mma16bf(acc[mi][ni], a[mi], bf[ni]);
            }
        } else {
#pragma unroll
            for (int ks = 0; ks < 4; ks++) {
                int base = ks * 8;
                unsigned a_hi[2][4], b_hi[4][2];
                float a_f[2][4], b_f[4][2];
#pragma unroll
                for (int mi = 0; mi < 2; mi++) {
                    int rb = wm*32 + mi*16;
                    a_f[mi][0] = Asb[(rb + g    )*36 + base + tig];
                    a_f[mi][1] = Asb[(rb + 8 + g)*36 + base + tig];
                    a_f[mi][2] = Asb[(rb + g    )*36 + base + tig + 4];
                    a_f[mi][3] = Asb[(rb + 8 + g)*36 + base + tig + 4];
#pragma unroll
                    for (int q = 0; q < 4; q++) a_hi[mi][q] = f2tf(a_f[mi][q]);
                }
#pragma unroll
                for (int ni = 0; ni < 4; ni++) {
                    int nb = wn*32 + ni*8;
                    b_f[ni][0] = Wsb[(nb + g)*36 + base + tig];
                    b_f[ni][1] = Wsb[(nb + g)*36 + base + tig + 4];
                    b_hi[ni][0] = f2tf(b_f[ni][0]);
                    b_hi[ni][1] = f2tf(b_f[ni][1]);
                }
                if (HILO) {
                    unsigned a_lo[2][4], b_lo[4][2];
#pragma unroll
                    for (int mi = 0; mi < 2; mi++)
#pragma unroll
                        for (int q = 0; q < 4; q++)
                            a_lo[mi][q] = f2tf(a_f[mi][q] - __uint_as_float(a_hi[mi][q]));
#pragma unroll
                    for (int ni = 0; ni < 4; ni++) {
                        b_lo[ni][0] = f2tf(b_f[ni][0] - __uint_as_float(b_hi[ni][0]));
                        b_lo[ni][1] = f2tf(b_f[ni][1] - __uint_as_float(b_hi[ni][1]));
                    }
#pragma unroll
                    for (int mi = 0; mi < 2; mi++)
#pragma unroll
                        for (int ni = 0; ni < 4; ni++) {
                            mma8(acc[mi][ni], a_hi[mi], b_lo[ni]);
                            mma8(acc[mi][ni], a_lo[mi], b_hi[ni]);
                            mma8(acc[mi][ni], a_hi[mi], b_hi[ni]);
                        }
                } else {
#pragma unroll
                    for (int mi = 0; mi < 2; mi++)
#pragma unroll
                        for (int ni = 0; ni < 4; ni++)
                            mma8(acc[mi][ni], a_hi[mi], b_hi[ni]);
                }
            }
        }
        __syncthreads();
    }

    // epilogue
#pragma unroll
    for (int mi = 0; mi < 2; mi++) {
#pragma unroll
        for (int ni = 0; ni < 4; ni++) {
            int cb = n0 + wn*32 + ni*8 + 2*tig;
            float2 bb = *(const float2*)&bias[cb];
#pragma unroll
            for (int h = 0; h < 2; h++) {
                int row = row0 + wm*32 + mi*16 + g + h*8;
                if (row >= S) continue;
                float v0 = acc[mi][ni][h*2 + 0] + bb.x;
                float v1 = acc[mi][ni][h*2 + 1] + bb.y;
                if (ACT == 1) {
                    v0 = 0.5f * v0 * (1.f + erff(v0 * 0.70710678118654752f));
                    v1 = 0.5f * v1 * (1.f + erff(v1 * 0.70710678118654752f));
                } else if (ACT == 2) {
                    v0 = v0 / (1.f + expf(-v0));
                    v1 = v1 / (1.f + expf(-v1));
                }
                if (RES) {
                    float2 rr = *(const float2*)&Rb[(size_t)row * N + cb];
                    v0 += rr.x; v1 += rr.y;
                }
                *(float2*)&Cb[(size_t)row * N + cb] = make_float2(v0, v1);
            }
        }
    }
}

// ---------------- logits: lf[p] = h1[p]·aw2 + ab2 (warp per pixel) --------------
__global__ void logits_kernel(const float* __restrict__ aw2,
                              const float* __restrict__ ab2)
{
    int p = blockIdx.x * 8 + (threadIdx.x >> 5);
    int lane = threadIdx.x & 31;
    const float* h = g_h1 + (size_t)p * AGH;
    float s = 0.f;
#pragma unroll
    for (int j = 0; j < 16; j++) s += h[lane + 32*j] * aw2[lane + 32*j];
#pragma unroll
    for (int o = 16; o > 0; o >>= 1) s += __shfl_xor_sync(0xffffffffu, s, o);
    if (lane == 0) g_lf[p] = s + ab2[0];
}

// ---------------- selection + top-64 fallback + compaction ----------------------
__global__ void select_kernel()
{
    __shared__ float vals[NTOK];
    __shared__ int   sels[NTOK];
    __shared__ int   wtot[8];
    __shared__ int   scount;
    __shared__ float rv[256];
    __shared__ int   ri[256];
    int b = blockIdx.x, tid = threadIdx.x;
    int lane = tid & 31, w = tid >> 5;

    int localc = 0;
    for (int n = tid; n < NTOK; n += 256) {
        float v = g_lf[b*NTOK + n];
        vals[n] = v;
        int s = (v > 0.f) ? 1 : 0;
        sels[n] = s;
        g_maskf[b*NTOK + n] = s ? 1.f : 0.f;
        localc += s;
    }
    {
        int c = localc;
#pragma unroll
        for (int o = 16; o > 0; o >>= 1) c += __shfl_xor_sync(0xffffffffu, c, o);
        if (lane == 0) wtot[w] = c;
        __syncthreads();
        if (tid == 0) { int t = 0; for (int i = 0; i < 8; i++) t += wtot[i]; scount = t; }
        __syncthreads();
    }
    int count = scount;

    if (count < 64) {
        for (int n = tid; n < NTOK; n += 256) sels[n] = 0;
        __syncthreads();
        for (int iter = 0; iter < 64; iter++) {
            float bv = -1e38f; int bi = NTOK;
            for (int n = tid; n < NTOK; n += 256)
                if (!sels[n] && vals[n] > bv) { bv = vals[n]; bi = n; }
            rv[tid] = bv; ri[tid] = bi;
            __syncthreads();
            for (int o = 128; o > 0; o >>= 1) {
                if (tid < o) {
                    if (rv[tid+o] > rv[tid] ||
                        (rv[tid+o] == rv[tid] && ri[tid+o] < ri[tid])) {
                        rv[tid] = rv[tid+o]; ri[tid] = ri[tid+o];
                    }
                }
                __syncthreads();
            }
            if (tid == 0) sels[ri[0]] = 1;
            __syncthreads();
        }
    }

    int base = tid * 9;
    int lc = 0;
#pragma unroll
    for (int k = 0; k < 9; k++) lc += sels[base + k];
    int inc = lc;
#pragma unroll
    for (int o = 1; o < 32; o <<= 1) {
        int v = __shfl_up_sync(0xffffffffu, inc, o);
        if (lane >= o) inc += v;
    }
    if (lane == 31) wtot[w] = inc;
    __syncthreads();
    if (tid < 8) {
        int v = wtot[tid];
#pragma unroll
        for (int o = 1; o < 8; o <<= 1) {
            int u = __shfl_up_sync(0xffu, v, o);
            if (tid >= o) v += u;
        }
        wtot[tid] = v;
    }
    __syncthreads();
    int pos = inc - lc + (w ? wtot[w-1] : 0);
    if (tid == 0) g_S[b] = wtot[7];
#pragma unroll
    for (int k = 0; k < 9; k++)
        if (sels[base + k]) g_idx[b*NTOK + pos++] = base + k;
}

// ---------------- gather compacted tokens (both modules) ------------------------
__global__ void gather_kernel()
{
    int b = blockIdx.y, s = blockIdx.x;
    if (s >= g_S[b]) return;
    int n = g_idx[b*NTOK + s];
    int c = threadIdx.x;
    const float* src = g_Xall + ((size_t)b*NTOK + n)*512;
    g_X[((size_t)b*NTOK + s)*DIM + c]        = src[c];
    g_X[((size_t)(NB + b)*NTOK + s)*DIM + c] = src[256 + c];
}

// ---------------- LayerNorm (warp per token) ------------------------------------
__global__ void ln_kernel(const float* __restrict__ X,
                          const float* __restrict__ g0, const float* __restrict__ b0_,
                          const float* __restrict__ g1, const float* __restrict__ b1_,
                          float* __restrict__ O)
{
    int z = blockIdx.y;
    int b = z & (NB - 1);
    int t = blockIdx.x * 8 + (threadIdx.x >> 5);
    if (t >= g_S[b]) return;
    const float* gg = (z < NB) ? g0 : g1;
    const float* bb = (z < NB) ? b0_ : b1_;
    int lane = threadIdx.x & 31;
    const float* x = X + ((size_t)z*NTOK + t)*DIM;
    float v[8];
    float s = 0.f;
#pragma unroll
    for (int j = 0; j < 8; j++) { v[j] = x[lane + 32*j]; s += v[j]; }
#pragma unroll
    for (int o = 16; o > 0; o >>= 1) s += __shfl_xor_sync(0xffffffffu, s, o);
    float mean = s * (1.f/256.f);
    float vs = 0.f;
#pragma unroll
    for (int j = 0; j < 8; j++) { float d = v[j] - mean; vs += d*d; }
#pragma unroll
    for (int o = 16; o > 0; o >>= 1) vs += __shfl_xor_sync(0xffffffffu, vs, o);
    float rstd = rsqrtf(vs * (1.f/256.f) + 1e-5f);
    float* o = O + ((size_t)z*NTOK + t)*DIM;
#pragma unroll
    for (int j = 0; j < 8; j++) {
        int c = lane + 32*j;
        o[c] = (v[j] - mean) * rstd * gg[c] + bb[c];
    }
}

// ---------------- flash attention, tf32 mma, scalar LDS (dh=64, 4 heads) --------
__global__ void flash_kernel()
{
    extern __shared__ unsigned fsm[];
    unsigned* Qs  = fsm;                 // [q][d] tf32, stride 68
    unsigned* Ks  = fsm + 64*68;         // [k][d] tf32
    unsigned* Vst = fsm + 2*64*68;       // [d][key] tf32 (transposed)
    float*    Ss  = (float*)(fsm + 3*64*68);   // [q][k] scores / p(tf32)
    unsigned* Psu = fsm + 3*64*68;
    __shared__ float m_s[64], l_s[64], al_s[64];

    int z = blockIdx.z;
    int b = z & (NB - 1);
    int h = blockIdx.y;
    int S = g_S[b];
    int qb = blockIdx.x * 64;
    if (qb >= S) return;
    int tid = threadIdx.x;
    int warp = tid >> 5, lane = tid & 31;
    int g = lane >> 2, tig = lane & 3;
    int wm = warp >> 1, wn = warp & 1;
    const float* qkvb = g_qkv + (size_t)z * NTOK * 768;

#pragma unroll
    for (int it = 0; it < 4; it++) {
        int lin = tid + it * 256;
        int r = lin >> 4, c4 = (lin & 15) * 4;
        int t = qb + r;
        float4 v = make_float4(0.f, 0.f, 0.f, 0.f);
        if (t < S) v = *(const float4*)&qkvb[(size_t)t*768 + h*64 + c4];
        uint4 hv; hv.x = f2tf(v.x); hv.y = f2tf(v.y); hv.z = f2tf(v.z); hv.w = f2tf(v.w);
        *(uint4*)&Qs[r*68 + c4] = hv;
    }
    if (tid < 64) { m_s[tid] = -1e30f; l_s[tid] = 0.f; }

    float oacc[4][4];
#pragma unroll
    for (int ni = 0; ni < 4; ni++)
#pragma unroll
        for (int q = 0; q < 4; q++) oacc[ni][q] = 0.f;

    for (int kb = 0; kb < S; kb += 64) {
        __syncthreads();
#pragma unroll
        for (int it = 0; it < 4; it++) {
            int lin = tid + it * 256;
            int r = lin >> 4, c4 = (lin & 15) * 4;
            int t = kb + r;
            float4 v = make_float4(0.f, 0.f, 0.f, 0.f);
            if (t < S) v = *(const float4*)&qkvb[(size_t)t*768 + 256 + h*64 + c4];
            uint4 hv; hv.x = f2tf(v.x); hv.y = f2tf(v.y); hv.z = f2tf(v.z); hv.w = f2tf(v.w);
            *(uint4*)&Ks[r*68 + c4] = hv;
        }
#pragma unroll
        for (int it = 0; it < 16; it++) {
            int lin = tid + it * 256;
            int d = lin & 63, tt = lin >> 6;
            int t = kb + tt;
            float v = (t < S) ? qkvb[(size_t)t*768 + 512 + h*64 + d] : 0.f;
            Vst[d*68 + tt] = f2tf(v);
        }
        __syncthreads();

        float sacc[4][4];
#pragma unroll
        for (int ni = 0; ni < 4; ni++)
#pragma unroll
            for (int q = 0; q < 4; q++) sacc[ni][q] = 0.f;
#pragma unroll
        for (int ks = 0; ks < 8; ks++) {
            int base = ks * 8;
            unsigned a[4];
            int rb = wm * 16;
            a[0] = Qs[(rb + g    )*68 + base + tig];
            a[1] = Qs[(rb + 8 + g)*68 + base + tig];
            a[2] = Qs[(rb + g    )*68 + base + tig + 4];
            a[3] = Qs[(rb + 8 + g)*68 + base + tig + 4];
#pragma unroll
            for (int ni = 0; ni < 4; ni++) {
                int key = wn*32 + ni*8 + g;
                unsigned bf[2];
                bf[0] = Ks[key*68 + base + tig];
                bf[1] = Ks[key*68 + base + tig + 4];
                mma8(sacc[ni], a, bf);
            }
        }
#pragma unroll
        for (int ni = 0; ni < 4; ni++) {
            int kcol = wn*32 + ni*8 + 2*tig;
            int q0 = wm*16 + g;
            float s0 = sacc[ni][0] * 0.125f, s1 = sacc[ni][1] * 0.125f;
            float s2 = sacc[ni][2] * 0.125f, s3 = sacc[ni][3] * 0.125f;
            if (kb + kcol     >= S) { s0 = -1e30f; s2 = -1e30f; }
            if (kb + kcol + 1 >= S) { s1 = -1e30f; s3 = -1e30f; }
            *(float2*)&Ss[q0*68 + kcol]     = make_float2(s0, s1);
            *(float2*)&Ss[(q0+8)*68 + kcol] = make_float2(s2, s3);
        }
        __syncthreads();

        {
            int row = tid >> 2, sub = tid & 3;
            float* Sr = Ss + row*68;
            float vv[16];
            float rm = -1e30f;
#pragma unroll
            for (int j = 0; j < 16; j++) { vv[j] = Sr[sub + 4*j]; rm = fmaxf(rm, vv[j]); }
            rm = fmaxf(rm, __shfl_xor_sync(0xffffffffu, rm, 1));
            rm = fmaxf(rm, __shfl_xor_sync(0xffffffffu, rm, 2));
            float mo = m_s[row];
            float mn = fmaxf(mo, rm);
            float rs = 0.f;
#pragma unroll
            for (int j = 0; j < 16; j++) {
                float p = __expf(vv[j] - mn);
                rs += p;
                Sr[sub + 4*j] = __uint_as_float(f2tf(p));
            }
            rs += __shfl_xor_sync(0xffffffffu, rs, 1);
            rs += __shfl_xor_sync(0xffffffffu, rs, 2);
            if (sub == 0) {
                float al = __expf(mo - mn);
                l_s[row] = l_s[row] * al + rs;
                m_s[row] = mn;
                al_s[row] = al;
            }
        }
        __syncthreads();

        {
            float al0 = al_s[wm*16 + g];
            float al1 = al_s[wm*16 + 8 + g];
#pragma unroll
            for (int ni = 0; ni < 4; ni++) {
                oacc[ni][0] *= al0; oacc[ni][1] *= al0;
                oacc[ni][2] *= al1; oacc[ni][3] *= al1;
            }
        }

#pragma unroll
        for (int ks = 0; ks < 8; ks++) {
            int base = ks * 8;
            unsigned a[4];
            int rb = wm * 16;
            a[0] = Psu[(rb + g    )*68 + base + tig];
            a[1] = Psu[(rb + 8 + g)*68 + base + tig];
            a[2] = Psu[(rb + g    )*68 + base + tig + 4];
            a[3] = Psu[(rb + 8 + g)*68 + base + tig + 4];
#pragma unroll
            for (int ni = 0; ni < 4; ni++) {
                int d = wn*32 + ni*8 + g;
                unsigned bf[2];
                bf[0] = Vst[d*68 + base + tig];
                bf[1] = Vst[d*68 + base + tig + 4];
                mma8(oacc[ni], a, bf);
            }
        }
    }

    {
        int q0 = wm*16 + g;
        float il0 = 1.f / l_s[q0];
        float il1 = 1.f / l_s[q0 + 8];
        int t0 = qb + q0, t1 = qb + q0 + 8;
        float* ab = g_attn + (size_t)z * NTOK * DIM;
#pragma unroll
        for (int ni = 0; ni < 4; ni++) {
            int d = h*64 + wn*32 + ni*8 + 2*tig;
            if (t0 < S)
                *(float2*)&ab[(size_t)t0*DIM + d] = make_float2(oacc[ni][0]*il0, oacc[ni][1]*il0);
            if (t1 < S)
                *(float2*)&ab[(size_t)t1*DIM + d] = make_float2(oacc[ni][2]*il1, oacc[ni][3]*il1);
        }
    }
}

// ---------------- final scatter -------------------------------------------------
__global__ void scatter_kernel(float* __restrict__ out)
{
    int b = blockIdx.y, s = blockIdx.x;
    if (s >= g_S[b]) return;
    int n = g_idx[b*NTOK + s];
    int c = threadIdx.x;
    float v = (g_mix[((size_t)b*NTOK + s)*DIM + c] +
               g_mix[((size_t)(NB + b)*NTOK + s)*DIM + c]) * g_maskf[b*NTOK + n];
    out[((size_t)b*DIM + c)*NTOK + n] = v;
}

// ---------------- host ----------------------------------------------------------
#define GETSYM(ptr, sym) cudaGetSymbolAddress((void**)&(ptr), sym)

extern "C" void kernel_launch(void* const* d_in, const int* in_sizes, int n_in,
                              void* d_out, int out_size)
{
    const float* f_ir  = (const float*)d_in[0];
    const float* f_vis = (const float*)d_in[1];
    const float* aw1   = (const float*)d_in[2];
    const float* ab1   = (const float*)d_in[3];
    const float* aw2   = (const float*)d_in[4];
    const float* ab2   = (const float*)d_in[5];
    const float* P[20];
    for (int i = 0; i < 20; i++) P[i] = (const float*)d_in[6 + i];
    float* out = (float*)d_out;

    float *p_Xall, *p_h1, *p_X, *p_xn, *p_qkv, *p_attn, *p_x1, *p_hff, *p_mix;
    GETSYM(p_Xall, g_Xall); GETSYM(p_h1, g_h1); GETSYM(p_X, g_X);
    GETSYM(p_xn, g_xn);     GETSYM(p_qkv, g_qkv); GETSYM(p_attn, g_attn);
    GETSYM(p_x1, g_x1);     GETSYM(p_hff, g_hff); GETSYM(p_mix, g_mix);

    const int SMG = 2*192*36*4;    // 55296 B : double-buffered fp32 tiles
    const int SMF = 4*64*68*4;     // 69632 B : flash

    cudaFuncSetAttribute(tgemm<2,false,false,true ,false>, cudaFuncAttributeMaxDynamicSharedMemorySize, SMG);
    cudaFuncSetAttribute(tgemm<0,false,true ,false,true >, cudaFuncAttributeMaxDynamicSharedMemorySize, SMG);
    cudaFuncSetAttribute(tgemm<0,true ,true ,false,true >, cudaFuncAttributeMaxDynamicSharedMemorySize, SMG);
    cudaFuncSetAttribute(tgemm<1,false,true ,false,true >, cudaFuncAttributeMaxDynamicSharedMemorySize, SMG);
    cudaFuncSetAttribute(flash_kernel, cudaFuncAttributeMaxDynamicSharedMemorySize, SMF);

    prep_kernel<<<dim3(72, 8, NB), dim3(32, 8)>>>(f_ir, f_vis, out);
    // agent: 3xTF32 (fp32-grade; logit sign decisions are razor-thin), silu
    tgemm<2,false,false,true,false><<<dim3(18, 8, NB), 256, SMG>>>(
        p_Xall, aw1, aw1, ab1, ab1, nullptr, p_h1, 512, 512);
    logits_kernel<<<1152, 256>>>(aw2, ab2);
    select_kernel<<<NB, 256>>>();
    gather_kernel<<<dim3(NTOK, NB), 256>>>();

    // fused ir+vis mixer pipeline (bf16 fragments over cp.async fp32 smem)
    ln_kernel<<<dim3(288, 8), 256>>>(p_X, P[0], P[1], P[10], P[11], p_xn);
    tgemm<0,false,true,false,true><<<dim3(18, 12, 8), 256, SMG>>>(
        p_xn, P[2], P[12], P[3], P[13], nullptr, p_qkv, 256, 768);
    flash_kernel<<<dim3(36, 4, 8), 256, SMF>>>();
    tgemm<0,true,true,false,true><<<dim3(18, 4, 8), 256, SMG>>>(
        p_attn, P[4], P[14], P[5], P[15], p_X, p_x1, 256, 256);
    ln_kernel<<<dim3(288, 8), 256>>>(p_x1, P[0], P[1], P[10], P[11], p_xn);
    tgemm<1,false,true,false,true><<<dim3(18, 16, 8), 256, SMG>>>(
        p_xn, P[6], P[16], P[7], P[17], nullptr, p_hff, 256, 1024);
    tgemm<0,true,true,false,true><<<dim3(18, 4, 8), 256, SMG>>>(
        p_hff, P[8], P[18], P[9], P[19], p_x1, p_mix, 1024, 256);

    scatter_kernel<<<dim3(NTOK, NB), 256>>>(out);
}

// round 14
// speedup vs baseline: 1.2000x; 1.1473x over previous
#include <cuda_runtime.h>
#include <cuda_fp16.h>
#include <math.h>

#define NB   4
#define NTOK 2304
#define DIM  256
#define AGH  512
#define AK   512
#define AN   512

// ---------------- scratch (device globals; no allocation allowed) ----------------
__device__ float g_Xall[NB*NTOK*512];          // [b][n][c] c=0..255 ir, 256..511 vis
__device__ float g_h1[NB*NTOK*AGH];
__device__ float g_lf[NB*NTOK];
__device__ float g_maskf[NB*NTOK];
__device__ int   g_idx[NB*NTOK];
__device__ int   g_S[NB];
__device__ float g_X[2*NB*NTOK*DIM];           // compacted tokens, slot = mod*NB+b
__device__ float g_xn[2*NB*NTOK*DIM];
__device__ float g_qkv[2*NB*NTOK*3*DIM];
__device__ float g_attn[2*NB*NTOK*DIM];
__device__ float g_x1[2*NB*NTOK*DIM];
__device__ float g_hff[2*NB*NTOK*4*DIM];
__device__ float g_mix[2*NB*NTOK*DIM];

// ---------------- tf32 / fp16 / cp.async helpers --------------------------------
__device__ __forceinline__ unsigned f2tf(float x) {
    unsigned u; asm("cvt.rna.tf32.f32 %0, %1;" : "=r"(u) : "f"(x)); return u;
}
__device__ __forceinline__ void mma8(float (&c)[4], const unsigned (&a)[4],
                                     const unsigned (&b)[2]) {
    asm volatile(
        "mma.sync.aligned.m16n8k8.row.col.f32.tf32.tf32.f32 "
        "{%0,%1,%2,%3}, {%4,%5,%6,%7}, {%8,%9}, {%0,%1,%2,%3};"
        : "+f"(c[0]), "+f"(c[1]), "+f"(c[2]), "+f"(c[3])
        : "r"(a[0]), "r"(a[1]), "r"(a[2]), "r"(a[3]), "r"(b[0]), "r"(b[1]));
}
__device__ __forceinline__ void mma16f(float (&c)[4], const unsigned (&a)[4],
                                       const unsigned (&b)[2]) {
    asm volatile(
        "mma.sync.aligned.m16n8k16.row.col.f32.f16.f16.f32 "
        "{%0,%1,%2,%3}, {%4,%5,%6,%7}, {%8,%9}, {%0,%1,%2,%3};"
        : "+f"(c[0]), "+f"(c[1]), "+f"(c[2]), "+f"(c[3])
        : "r"(a[0]), "r"(a[1]), "r"(a[2]), "r"(a[3]), "r"(b[0]), "r"(b[1]));
}
// two-limb fp16 split of a float pair -> packed hi pair + lo pair
__device__ __forceinline__ void split2(float x0, float x1, unsigned &hp, unsigned &lp) {
    __half h0 = __float2half_rn(x0), h1 = __float2half_rn(x1);
    __half l0 = __float2half_rn(x0 - __half2float(h0));
    __half l1 = __float2half_rn(x1 - __half2float(h1));
    __half2 hh = __halves2half2(h0, h1);
    __half2 ll = __halves2half2(l0, l1);
    hp = *reinterpret_cast<unsigned*>(&hh);
    lp = *reinterpret_cast<unsigned*>(&ll);
}
__device__ __forceinline__ void cpa16(float* dst, const float* src, bool pred) {
    unsigned d = (unsigned)__cvta_generic_to_shared(dst);
    int sz = pred ? 16 : 0;
    asm volatile("cp.async.cg.shared.global [%0], [%1], 16, %2;"
                 :: "r"(d), "l"(src), "r"(sz));
}
#define CP_COMMIT() asm volatile("cp.async.commit_group;" ::: "memory")

// ---------------- prep: transpose to token-major concat + base canvas -----------
__global__ void prep_kernel(const float* __restrict__ f_ir,
                            const float* __restrict__ f_vis,
                            float* __restrict__ out)
{
    __shared__ float ti[32][33], tv[32][33];
    int b = blockIdx.z;
    int c0 = blockIdx.y * 32;
    int n0 = blockIdx.x * 32;
#pragma unroll
    for (int i = 0; i < 4; i++) {
        int c = c0 + threadIdx.y + i * 8;
        size_t off = ((size_t)b*256 + c)*NTOK + n0 + threadIdx.x;
        float vi = f_ir[off], vv = f_vis[off];
        ti[threadIdx.y + i*8][threadIdx.x] = vi;
        tv[threadIdx.y + i*8][threadIdx.x] = vv;
        out[off] = vi + vv;
    }
    __syncthreads();
#pragma unroll
    for (int i = 0; i < 4; i++) {
        int n = n0 + threadIdx.y + i * 8;
        size_t base = ((size_t)b*NTOK + n)*512;
        g_Xall[base + c0 + threadIdx.x]       = ti[threadIdx.x][threadIdx.y + i*8];
        g_Xall[base + 256 + c0 + threadIdx.x] = tv[threadIdx.x][threadIdx.y + i*8];
    }
}

// ---------------- agent GEMM: two-limb fp16, mma.m16n8k16 -----------------------
// h1 = silu(Xall @ aw1^T + ab1). fp32-grade: hi*hi + hi*lo + lo*hi (residual ~2^-21).
// Limbs packed at staging (once per element); inner loop = pure LDS + mma.
// block tile 128(M) x 64(N), K-chunk 32, 8 warps (4M x 2N). 2304 % 128 == 0.
__global__ void __launch_bounds__(256) agemm(const float* __restrict__ A,
                                             const float* __restrict__ W,
                                             const float* __restrict__ bias,
                                             float* __restrict__ C)
{
    int z = blockIdx.z;
    int row0 = blockIdx.x * 128;
    int n0 = blockIdx.y * 64;
    const float* Ab = A + (size_t)z * NTOK * AK;
    float*       Cb = C + (size_t)z * NTOK * AN;

    __shared__ unsigned As_hi[128*20], As_lo[128*20];
    __shared__ unsigned Ws_hi[64*20],  Ws_lo[64*20];

    int tid = threadIdx.x;
    int warp = tid >> 5, lane = tid & 31;
    int g = lane >> 2, tig = lane & 3;
    int wm = warp >> 1, wn = warp & 1;

    int arow = tid >> 1, ahalf = (tid & 1) * 16;   // 2 threads/row, 16 floats each
    int wrow = tid >> 2, wquart = (tid & 3) * 8;   // 4 threads/row, 8 floats each

    float acc[2][4][4];
#pragma unroll
    for (int mi = 0; mi < 2; mi++)
#pragma unroll
        for (int ni = 0; ni < 4; ni++)
#pragma unroll
            for (int q = 0; q < 4; q++) acc[mi][ni][q] = 0.f;

    for (int k0 = 0; k0 < AK; k0 += 32) {
        // stage A: 16 floats -> 8 hi pairs + 8 lo pairs
        {
            const float* p = &Ab[(size_t)(row0 + arow) * AK + k0 + ahalf];
            unsigned hp[8], lp[8];
#pragma unroll
            for (int i = 0; i < 4; i++) {
                float4 v = *(const float4*)(p + 4*i);
                split2(v.x, v.y, hp[2*i],   lp[2*i]);
                split2(v.z, v.w, hp[2*i+1], lp[2*i+1]);
            }
            int off = arow*20 + (ahalf >> 1);
            *(uint4*)&As_hi[off]     = make_uint4(hp[0], hp[1], hp[2], hp[3]);
            *(uint4*)&As_hi[off + 4] = make_uint4(hp[4], hp[5], hp[6], hp[7]);
            *(uint4*)&As_lo[off]     = make_uint4(lp[0], lp[1], lp[2], lp[3]);
            *(uint4*)&As_lo[off + 4] = make_uint4(lp[4], lp[5], lp[6], lp[7]);
        }
        // stage W: 8 floats -> 4 hi pairs + 4 lo pairs
        {
            const float* p = &W[(size_t)(n0 + wrow) * AK + k0 + wquart];
            float4 v0 = *(const float4*)(p);
            float4 v1 = *(const float4*)(p + 4);
            unsigned hp[4], lp[4];
            split2(v0.x, v0.y, hp[0], lp[0]);
            split2(v0.z, v0.w, hp[1], lp[1]);
            split2(v1.x, v1.y, hp[2], lp[2]);
            split2(v1.z, v1.w, hp[3], lp[3]);
            int off = wrow*20 + (wquart >> 1);
            *(uint4*)&Ws_hi[off] = make_uint4(hp[0], hp[1], hp[2], hp[3]);
            *(uint4*)&Ws_lo[off] = make_uint4(lp[0], lp[1], lp[2], lp[3]);
        }
        __syncthreads();

#pragma unroll
        for (int ks = 0; ks < 2; ks++) {           // two k16 slabs per chunk
            int base = ks * 8;
            unsigned ah[2][4], al[2][4], bh[4][2], bl[4][2];
#pragma unroll
            for (int mi = 0; mi < 2; mi++) {
                int rb = wm*32 + mi*16;
                ah[mi][0] = As_hi[(rb + g    )*20 + base + tig];
                ah[mi][1] = As_hi[(rb + 8 + g)*20 + base + tig];
                ah[mi][2] = As_hi[(rb + g    )*20 + base + tig + 4];
                ah[mi][3] = As_hi[(rb + 8 + g)*20 + base + tig + 4];
                al[mi][0] = As_lo[(rb + g    )*20 + base + tig];
                al[mi][1] = As_lo[(rb + 8 + g)*20 + base + tig];
                al[mi][2] = As_lo[(rb + g    )*20 + base + tig + 4];
                al[mi][3] = As_lo[(rb + 8 + g)*20 + base + tig + 4];
            }
#pragma unroll
            for (int ni = 0; ni < 4; ni++) {
                int nb = wn*32 + ni*8;
                bh[ni][0] = Ws_hi[(nb + g)*20 + base + tig];
                bh[ni][1] = Ws_hi[(nb + g)*20 + base + tig + 4];
                bl[ni][0] = Ws_lo[(nb + g)*20 + base + tig];
                bl[ni][1] = Ws_lo[(nb + g)*20 + base + tig + 4];
            }
#pragma unroll
            for (int mi = 0; mi < 2; mi++)
#pragma unroll
                for (int ni = 0; ni < 4; ni++) {
                    mma16f(acc[mi][ni], ah[mi], bl[ni]);
                    mma16f(acc[mi][ni], al[mi], bh[ni]);
                    mma16f(acc[mi][ni], ah[mi], bh[ni]);
                }
        }
        __syncthreads();
    }

    // epilogue: bias + silu (rows always in range)
#pragma unroll
    for (int mi = 0; mi < 2; mi++) {
#pragma unroll
        for (int ni = 0; ni < 4; ni++) {
            int cb = n0 + wn*32 + ni*8 + 2*tig;
            float2 bb = *(const float2*)&bias[cb];
#pragma unroll
            for (int h = 0; h < 2; h++) {
                int row = row0 + wm*32 + mi*16 + g + h*8;
                float v0 = acc[mi][ni][h*2 + 0] + bb.x;
                float v1 = acc[mi][ni][h*2 + 1] + bb.y;
                v0 = v0 / (1.f + expf(-v0));
                v1 = v1 / (1.f + expf(-v1));
                *(float2*)&Cb[(size_t)row * AN + cb] = make_float2(v0, v1);
            }
        }
    }
}

// ---------------- mixer tf32 GEMM, cp.async double-buffer (R9-proven) -----------
template<int ACT, bool RES>
__global__ void __launch_bounds__(256) tgemm(
                      const float* __restrict__ A,
                      const float* __restrict__ W0, const float* __restrict__ W1,
                      const float* __restrict__ bias0, const float* __restrict__ bias1,
                      const float* __restrict__ R, float* __restrict__ C,
                      int K, int N)
{
    int z = blockIdx.z;
    int b = z & (NB - 1);
    int S = g_S[b];
    int row0 = blockIdx.x * 128;
    if (row0 >= S) return;
    const float* W    = (z < NB) ? W0 : W1;
    const float* bias = (z < NB) ? bias0 : bias1;
    int n0 = blockIdx.y * 64;
    const float* Ab = A + (size_t)z * NTOK * K;
    float*       Cb = C + (size_t)z * NTOK * N;
    const float* Rb = RES ? (R + (size_t)z * NTOK * N) : nullptr;

    extern __shared__ float sh[];                    // 2 x (A 128*36 + W 64*36)
    float* Abuf[2] = { sh,            sh + 192*36 };
    float* Wbuf[2] = { sh + 128*36,   sh + 320*36 };

    int tid  = threadIdx.x;
    int warp = tid >> 5, lane = tid & 31;
    int g = lane >> 2, tig = lane & 3;
    int wm = warp >> 1, wn = warp & 1;

    int ar  = tid >> 3;
    int ac4 = (tid & 7) * 4;

    float acc[2][4][4];
#pragma unroll
    for (int mi = 0; mi < 2; mi++)
#pragma unroll
        for (int ni = 0; ni < 4; ni++)
#pragma unroll
            for (int q = 0; q < 4; q++) acc[mi][ni][q] = 0.f;

    const int NCH = K >> 5;

    auto issue = [&](int c, int bi) {
        int kc = c * 32;
#pragma unroll
        for (int it = 0; it < 4; it++) {
            int r = ar + it * 32;
            int row = row0 + r;
            bool ok = (row < S);
            cpa16(&Abuf[bi][r*36 + ac4], &Ab[(size_t)(ok ? row : 0) * K + kc + ac4], ok);
        }
#pragma unroll
        for (int it = 0; it < 2; it++) {
            int r = ar + it * 32;
            cpa16(&Wbuf[bi][r*36 + ac4], &W[(size_t)(n0 + r) * K + kc + ac4], true);
        }
    };

    issue(0, 0);
    CP_COMMIT();

    for (int c = 0; c < NCH; c++) {
        int cur = c & 1;
        if (c + 1 < NCH) { issue(c + 1, cur ^ 1); CP_COMMIT(); }
        if (c + 1 < NCH) asm volatile("cp.async.wait_group 1;" ::: "memory");
        else             asm volatile("cp.async.wait_group 0;" ::: "memory");
        __syncthreads();

        const float* Asb = Abuf[cur];
        const float* Wsb = Wbuf[cur];
#pragma unroll
        for (int ks = 0; ks < 4; ks++) {
            int base = ks * 8;
            unsigned a_hi[2][4], b_hi[4][2];
#pragma unroll
            for (int mi = 0; mi < 2; mi++) {
                int rb = wm*32 + mi*16;
                a_hi[mi][0] = f2tf(Asb[(rb + g    )*36 + base + tig]);
                a_hi[mi][1] = f2tf(Asb[(rb + 8 + g)*36 + base + tig]);
                a_hi[mi][2] = f2tf(Asb[(rb + g    )*36 + base + tig + 4]);
                a_hi[mi][3] = f2tf(Asb[(rb + 8 + g)*36 + base + tig + 4]);
            }
#pragma unroll
            for (int ni = 0; ni < 4; ni++) {
                int nb = wn*32 + ni*8;
                b_hi[ni][0] = f2tf(Wsb[(nb + g)*36 + base + tig]);
                b_hi[ni][1] = f2tf(Wsb[(nb + g)*36 + base + tig + 4]);
            }
#pragma unroll
            for (int mi = 0; mi < 2; mi++)
#pragma unroll
                for (int ni = 0; ni < 4; ni++)
                    mma8(acc[mi][ni], a_hi[mi], b_hi[ni]);
        }
        __syncthreads();
    }

#pragma unroll
    for (int mi = 0; mi < 2; mi++) {
#pragma unroll
        for (int ni = 0; ni < 4; ni++) {
            int cb = n0 + wn*32 + ni*8 + 2*tig;
            float2 bb = *(const float2*)&bias[cb];
#pragma unroll
            for (int h = 0; h < 2; h++) {
                int row = row0 + wm*32 + mi*16 + g + h*8;
                if (row >= S) continue;
                float v0 = acc[mi][ni][h*2 + 0] + bb.x;
                float v1 = acc[mi][ni][h*2 + 1] + bb.y;
                if (ACT == 1) {
                    v0 = 0.5f * v0 * (1.f + erff(v0 * 0.70710678118654752f));
                    v1 = 0.5f * v1 * (1.f + erff(v1 * 0.70710678118654752f));
                }
                if (RES) {
                    float2 rr = *(const float2*)&Rb[(size_t)row * N + cb];
                    v0 += rr.x; v1 += rr.y;
                }
                *(float2*)&Cb[(size_t)row * N + cb] = make_float2(v0, v1);
            }
        }
    }
}

// ---------------- logits: lf[p] = h1[p]·aw2 + ab2 (warp per pixel) --------------
__global__ void logits_kernel(const float* __restrict__ aw2,
                              const float* __restrict__ ab2)
{
    int p = blockIdx.x * 8 + (threadIdx.x >> 5);
    int lane = threadIdx.x & 31;
    const float* h = g_h1 + (size_t)p * AGH;
    float s = 0.f;
#pragma unroll
    for (int j = 0; j < 16; j++) s += h[lane + 32*j] * aw2[lane + 32*j];
#pragma unroll
    for (int o = 16; o > 0; o >>= 1) s += __shfl_xor_sync(0xffffffffu, s, o);
    if (lane == 0) g_lf[p] = s + ab2[0];
}

// ---------------- selection + top-64 fallback + compaction ----------------------
__global__ void select_kernel()
{
    __shared__ float vals[NTOK];
    __shared__ int   sels[NTOK];
    __shared__ int   wtot[8];
    __shared__ int   scount;
    __shared__ float rv[256];
    __shared__ int   ri[256];
    int b = blockIdx.x, tid = threadIdx.x;
    int lane = tid & 31, w = tid >> 5;

    int localc = 0;
    for (int n = tid; n < NTOK; n += 256) {
        float v = g_lf[b*NTOK + n];
        vals[n] = v;
        int s = (v > 0.f) ? 1 : 0;
        sels[n] = s;
        g_maskf[b*NTOK + n] = s ? 1.f : 0.f;
        localc += s;
    }
    {
        int c = localc;
#pragma unroll
        for (int o = 16; o > 0; o >>= 1) c += __shfl_xor_sync(0xffffffffu, c, o);
        if (lane == 0) wtot[w] = c;
        __syncthreads();
        if (tid == 0) { int t = 0; for (int i = 0; i < 8; i++) t += wtot[i]; scount = t; }
        __syncthreads();
    }
    int count = scount;

    if (count < 64) {
        for (int n = tid; n < NTOK; n += 256) sels[n] = 0;
        __syncthreads();
        for (int iter = 0; iter < 64; iter++) {
            float bv = -1e38f; int bi = NTOK;
            for (int n = tid; n < NTOK; n += 256)
                if (!sels[n] && vals[n] > bv) { bv = vals[n]; bi = n; }
            rv[tid] = bv; ri[tid] = bi;
            __syncthreads();
            for (int o = 128; o > 0; o >>= 1) {
                if (tid < o) {
                    if (rv[tid+o] > rv[tid] ||
                        (rv[tid+o] == rv[tid] && ri[tid+o] < ri[tid])) {
                        rv[tid] = rv[tid+o]; ri[tid] = ri[tid+o];
                    }
                }
                __syncthreads();
            }
            if (tid == 0) sels[ri[0]] = 1;
            __syncthreads();
        }
    }

    int base = tid * 9;
    int lc = 0;
#pragma unroll
    for (int k = 0; k < 9; k++) lc += sels[base + k];
    int inc = lc;
#pragma unroll
    for (int o = 1; o < 32; o <<= 1) {
        int v = __shfl_up_sync(0xffffffffu, inc, o);
        if (lane >= o) inc += v;
    }
    if (lane == 31) wtot[w] = inc;
    __syncthreads();
    if (tid < 8) {
        int v = wtot[tid];
#pragma unroll
        for (int o = 1; o < 8; o <<= 1) {
            int u = __shfl_up_sync(0xffu, v, o);
            if (tid >= o) v += u;
        }
        wtot[tid] = v;
    }
    __syncthreads();
    int pos = inc - lc + (w ? wtot[w-1] : 0);
    if (tid == 0) g_S[b] = wtot[7];
#pragma unroll
    for (int k = 0; k < 9; k++)
        if (sels[base + k]) g_idx[b*NTOK + pos++] = base + k;
}

// ---------------- gather compacted tokens (both modules) ------------------------
__global__ void gather_kernel()
{
    int b = blockIdx.y, s = blockIdx.x;
    if (s >= g_S[b]) return;
    int n = g_idx[b*NTOK + s];
    int c = threadIdx.x;
    const float* src = g_Xall + ((size_t)b*NTOK + n)*512;
    g_X[((size_t)b*NTOK + s)*DIM + c]        = src[c];
    g_X[((size_t)(NB + b)*NTOK + s)*DIM + c] = src[256 + c];
}

// ---------------- LayerNorm (warp per token) ------------------------------------
__global__ void ln_kernel(const float* __restrict__ X,
                          const float* __restrict__ g0, const float* __restrict__ b0_,
                          const float* __restrict__ g1, const float* __restrict__ b1_,
                          float* __restrict__ O)
{
    int z = blockIdx.y;
    int b = z & (NB - 1);
    int t = blockIdx.x * 8 + (threadIdx.x >> 5);
    if (t >= g_S[b]) return;
    const float* gg = (z < NB) ? g0 : g1;
    const float* bb = (z < NB) ? b0_ : b1_;
    int lane = threadIdx.x & 31;
    const float* x = X + ((size_t)z*NTOK + t)*DIM;
    float v[8];
    float s = 0.f;
#pragma unroll
    for (int j = 0; j < 8; j++) { v[j] = x[lane + 32*j]; s += v[j]; }
#pragma unroll
    for (int o = 16; o > 0; o >>= 1) s += __shfl_xor_sync(0xffffffffu, s, o);
    float mean = s * (1.f/256.f);
    float vs = 0.f;
#pragma unroll
    for (int j = 0; j < 8; j++) { float d = v[j] - mean; vs += d*d; }
#pragma unroll
    for (int o = 16; o > 0; o >>= 1) vs += __shfl_xor_sync(0xffffffffu, vs, o);
    float rstd = rsqrtf(vs * (1.f/256.f) + 1e-5f);
    float* o = O + ((size_t)z*NTOK + t)*DIM;
#pragma unroll
    for (int j = 0; j < 8; j++) {
        int c = lane + 32*j;
        o[c] = (v[j] - mean) * rstd * gg[c] + bb[c];
    }
}

// ---------------- flash attention, tf32 mma, scalar LDS (dh=64, 4 heads) --------
__global__ void flash_kernel()
{
    extern __shared__ unsigned fsm[];
    unsigned* Qs  = fsm;                 // [q][d] tf32, stride 68
    unsigned* Ks  = fsm + 64*68;         // [k][d] tf32
    unsigned* Vst = fsm + 2*64*68;       // [d][key] tf32 (transposed)
    float*    Ss  = (float*)(fsm + 3*64*68);   // [q][k] scores / p(tf32)
    unsigned* Psu = fsm + 3*64*68;
    __shared__ float m_s[64], l_s[64], al_s[64];

    int z = blockIdx.z;
    int b = z & (NB - 1);
    int h = blockIdx.y;
    int S = g_S[b];
    int qb = blockIdx.x * 64;
    if (qb >= S) return;
    int tid = threadIdx.x;
    int warp = tid >> 5, lane = tid & 31;
    int g = lane >> 2, tig = lane & 3;
    int wm = warp >> 1, wn = warp & 1;
    const float* qkvb = g_qkv + (size_t)z * NTOK * 768;

#pragma unroll
    for (int it = 0; it < 4; it++) {
        int lin = tid + it * 256;
        int r = lin >> 4, c4 = (lin & 15) * 4;
        int t = qb + r;
        float4 v = make_float4(0.f, 0.f, 0.f, 0.f);
        if (t < S) v = *(const float4*)&qkvb[(size_t)t*768 + h*64 + c4];
        uint4 hv; hv.x = f2tf(v.x); hv.y = f2tf(v.y); hv.z = f2tf(v.z); hv.w = f2tf(v.w);
        *(uint4*)&Qs[r*68 + c4] = hv;
    }
    if (tid < 64) { m_s[tid] = -1e30f; l_s[tid] = 0.f; }

    float oacc[4][4];
#pragma unroll
    for (int ni = 0; ni < 4; ni++)
#pragma unroll
        for (int q = 0; q < 4; q++) oacc[ni][q] = 0.f;

    for (int kb = 0; kb < S; kb += 64) {
        __syncthreads();
#pragma unroll
        for (int it = 0; it < 4; it++) {
            int lin = tid + it * 256;
            int r = lin >> 4, c4 = (lin & 15) * 4;
            int t = kb + r;
            float4 v = make_float4(0.f, 0.f, 0.f, 0.f);
            if (t < S) v = *(const float4*)&qkvb[(size_t)t*768 + 256 + h*64 + c4];
            uint4 hv; hv.x = f2tf(v.x); hv.y = f2tf(v.y); hv.z = f2tf(v.z); hv.w = f2tf(v.w);
            *(uint4*)&Ks[r*68 + c4] = hv;
        }
#pragma unroll
        for (int it = 0; it < 16; it++) {
            int lin = tid + it * 256;
            int d = lin & 63, tt = lin >> 6;
            int t = kb + tt;
            float v = (t < S) ? qkvb[(size_t)t*768 + 512 + h*64 + d] : 0.f;
            Vst[d*68 + tt] = f2tf(v);
        }
        __syncthreads();

        float sacc[4][4];
#pragma unroll
        for (int ni = 0; ni < 4; ni++)
#pragma unroll
            for (int q = 0; q < 4; q++) sacc[ni][q] = 0.f;
#pragma unroll
        for (int ks = 0; ks < 8; ks++) {
            int base = ks * 8;
            unsigned a[4];
            int rb = wm * 16;
            a[0] = Qs[(rb + g    )*68 + base + tig];
            a[1] = Qs[(rb + 8 + g)*68 + base + tig];
            a[2] = Qs[(rb + g    )*68 + base + tig + 4];
            a[3] = Qs[(rb + 8 + g)*68 + base + tig + 4];
#pragma unroll
            for (int ni = 0; ni < 4; ni++) {
                int key = wn*32 + ni*8 + g;
                unsigned bf[2];
                bf[0] = Ks[key*68 + base + tig];
                bf[1] = Ks[key*68 + base + tig + 4];
                mma8(sacc[ni], a, bf);
            }
        }
#pragma unroll
        for (int ni = 0; ni < 4; ni++) {
            int kcol = wn*32 + ni*8 + 2*tig;
            int q0 = wm*16 + g;
            float s0 = sacc[ni][0] * 0.125f, s1 = sacc[ni][1] * 0.125f;
            float s2 = sacc[ni][2] * 0.125f, s3 = sacc[ni][3] * 0.125f;
            if (kb + kcol     >= S) { s0 = -1e30f; s2 = -1e30f; }
            if (kb + kcol + 1 >= S) { s1 = -1e30f; s3 = -1e30f; }
            *(float2*)&Ss[q0*68 + kcol]     = make_float2(s0, s1);
            *(float2*)&Ss[(q0+8)*68 + kcol] = make_float2(s2, s3);
        }
        __syncthreads();

        {
            int row = tid >> 2, sub = tid & 3;
            float* Sr = Ss + row*68;
            float vv[16];
            float rm = -1e30f;
#pragma unroll
            for (int j = 0; j < 16; j++) { vv[j] = Sr[sub + 4*j]; rm = fmaxf(rm, vv[j]); }
            rm = fmaxf(rm, __shfl_xor_sync(0xffffffffu, rm, 1));
            rm = fmaxf(rm, __shfl_xor_sync(0xffffffffu, rm, 2));
            float mo = m_s[row];
            float mn = fmaxf(mo, rm);
            float rs = 0.f;
#pragma unroll
            for (int j = 0; j < 16; j++) {
                float p = __expf(vv[j] - mn);
                rs += p;
                Sr[sub + 4*j] = __uint_as_float(f2tf(p));
            }
            rs += __shfl_xor_sync(0xffffffffu, rs, 1);
            rs += __shfl_xor_sync(0xffffffffu, rs, 2);
            if (sub == 0) {
                float al = __expf(mo - mn);
                l_s[row] = l_s[row] * al + rs;
                m_s[row] = mn;
                al_s[row] = al;
            }
        }
        __syncthreads();

        {
            float al0 = al_s[wm*16 + g];
            float al1 = al_s[wm*16 + 8 + g];
#pragma unroll
            for (int ni = 0; ni < 4; ni++) {
                oacc[ni][0] *= al0; oacc[ni][1] *= al0;
                oacc[ni][2] *= al1; oacc[ni][3] *= al1;
            }
        }

#pragma unroll
        for (int ks = 0; ks < 8; ks++) {
            int base = ks * 8;
            unsigned a[4];
            int rb = wm * 16;
            a[0] = Psu[(rb + g    )*68 + base + tig];
            a[1] = Psu[(rb + 8 + g)*68 + base + tig];
            a[2] = Psu[(rb + g    )*68 + base + tig + 4];
            a[3] = Psu[(rb + 8 + g)*68 + base + tig + 4];
#pragma unroll
            for (int ni = 0; ni < 4; ni++) {
                int d = wn*32 + ni*8 + g;
                unsigned bf[2];
                bf[0] = Vst[d*68 + base + tig];
                bf[1] = Vst[d*68 + base + tig + 4];
                mma8(oacc[ni], a, bf);
            }
        }
    }

    {
        int q0 = wm*16 + g;
        float il0 = 1.f / l_s[q0];
        float il1 = 1.f / l_s[q0 + 8];
        int t0 = qb + q0, t1 = qb + q0 + 8;
        float* ab = g_attn + (size_t)z * NTOK * DIM;
#pragma unroll
        for (int ni = 0; ni < 4; ni++) {
            int d = h*64 + wn*32 + ni*8 + 2*tig;
            if (t0 < S)
                *(float2*)&ab[(size_t)t0*DIM + d] = make_float2(oacc[ni][0]*il0, oacc[ni][1]*il0);
            if (t1 < S)
                *(float2*)&ab[(size_t)t1*DIM + d] = make_float2(oacc[ni][2]*il1, oacc[ni][3]*il1);
        }
    }
}

// ---------------- final scatter -------------------------------------------------
__global__ void scatter_kernel(float* __restrict__ out)
{
    int b = blockIdx.y, s = blockIdx.x;
    if (s >= g_S[b]) return;
    int n = g_idx[b*NTOK + s];
    int c = threadIdx.x;
    float v = (g_mix[((size_t)b*NTOK + s)*DIM + c] +
               g_mix[((size_t)(NB + b)*NTOK + s)*DIM + c]) * g_maskf[b*NTOK + n];
    out[((size_t)b*DIM + c)*NTOK + n] = v;
}

// ---------------- host ----------------------------------------------------------
#define GETSYM(ptr, sym) cudaGetSymbolAddress((void**)&(ptr), sym)

extern "C" void kernel_launch(void* const* d_in, const int* in_sizes, int n_in,
                              void* d_out, int out_size)
{
    const float* f_ir  = (const float*)d_in[0];
    const float* f_vis = (const float*)d_in[1];
    const float* aw1   = (const float*)d_in[2];
    const float* ab1   = (const float*)d_in[3];
    const float* aw2   = (const float*)d_in[4];
    const float* ab2   = (const float*)d_in[5];
    const float* P[20];
    for (int i = 0; i < 20; i++) P[i] = (const float*)d_in[6 + i];
    float* out = (float*)d_out;

    float *p_Xall, *p_h1, *p_X, *p_xn, *p_qkv, *p_attn, *p_x1, *p_hff, *p_mix;
    GETSYM(p_Xall, g_Xall); GETSYM(p_h1, g_h1); GETSYM(p_X, g_X);
    GETSYM(p_xn, g_xn);     GETSYM(p_qkv, g_qkv); GETSYM(p_attn, g_attn);
    GETSYM(p_x1, g_x1);     GETSYM(p_hff, g_hff); GETSYM(p_mix, g_mix);

    const int SMG = 2*192*36*4;    // 55296 B : double-buffered fp32 tiles
    const int SMF = 4*64*68*4;     // 69632 B : flash

    cudaFuncSetAttribute(tgemm<0,false>, cudaFuncAttributeMaxDynamicSharedMemorySize, SMG);
    cudaFuncSetAttribute(tgemm<0,true >, cudaFuncAttributeMaxDynamicSharedMemorySize, SMG);
    cudaFuncSetAttribute(tgemm<1,false>, cudaFuncAttributeMaxDynamicSharedMemorySize, SMG);
    cudaFuncSetAttribute(flash_kernel, cudaFuncAttributeMaxDynamicSharedMemorySize, SMF);

    prep_kernel<<<dim3(72, 8, NB), dim3(32, 8)>>>(f_ir, f_vis, out);
    // agent: two-limb fp16 (fp32-grade, 2x tensor rate vs 3xTF32), silu
    agemm<<<dim3(18, 8, NB), 256>>>(p_Xall, aw1, ab1, p_h1);
    logits_kernel<<<1152, 256>>>(aw2, ab2);
    select_kernel<<<NB, 256>>>();
    gather_kernel<<<dim3(NTOK, NB), 256>>>();

    // fused ir+vis mixer pipeline (tf32, R9-proven): z = mod*NB + b (8 slots)
    ln_kernel<<<dim3(288, 8), 256>>>(p_X, P[0], P[1], P[10], P[11], p_xn);
    tgemm<0,false><<<dim3(18, 12, 8), 256, SMG>>>(
        p_xn, P[2], P[12], P[3], P[13], nullptr, p_qkv, 256, 768);
    flash_kernel<<<dim3(36, 4, 8), 256, SMF>>>();
    tgemm<0,true><<<dim3(18, 4, 8), 256, SMG>>>(
        p_attn, P[4], P[14], P[5], P[15], p_X, p_x1, 256, 256);
    ln_kernel<<<dim3(288, 8), 256>>>(p_x1, P[0], P[1], P[10], P[11], p_xn);
    tgemm<1,false><<<dim3(18, 16, 8), 256, SMG>>>(
        p_xn, P[6], P[16], P[7], P[17], nullptr, p_hff, 256, 1024);
    tgemm<0,true><<<dim3(18, 4, 8), 256, SMG>>>(
        p_hff, P[8], P[18], P[9], P[19], p_x1, p_mix, 1024, 256);

    scatter_kernel<<<dim3(NTOK, NB), 256>>>(out);
}

// round 15
// speedup vs baseline: 1.5408x; 1.2840x over previous
#include <cuda_runtime.h>
#include <cuda_fp16.h>
#include <math.h>

#define NB   4
#define NTOK 2304
#define DIM  256
#define AGH  512
#define AK   512
#define AN   512

// ---------------- scratch (device globals; no allocation allowed) ----------------
__device__ float g_Xall[NB*NTOK*512];          // [b][n][c] c=0..255 ir, 256..511 vis
__device__ float g_h1[NB*NTOK*AGH];
__device__ float g_lf[NB*NTOK];
__device__ float g_maskf[NB*NTOK];
__device__ int   g_idx[NB*NTOK];
__device__ int   g_S[NB];
__device__ float g_X[2*NB*NTOK*DIM];           // compacted tokens, slot = mod*NB+b
__device__ float g_xn[2*NB*NTOK*DIM];
__device__ float g_qkv[2*NB*NTOK*3*DIM];
__device__ float g_attn[2*NB*NTOK*DIM];
__device__ float g_x1[2*NB*NTOK*DIM];
__device__ float g_hff[2*NB*NTOK*4*DIM];
__device__ float g_mix[2*NB*NTOK*DIM];

// ---------------- tf32 / fp16 / cp.async helpers --------------------------------
__device__ __forceinline__ unsigned f2tf(float x) {
    unsigned u; asm("cvt.rna.tf32.f32 %0, %1;" : "=r"(u) : "f"(x)); return u;
}
__device__ __forceinline__ unsigned pack_f16(float lo, float hi) {
    unsigned r; asm("cvt.rn.f16x2.f32 %0, %1, %2;" : "=r"(r) : "f"(hi), "f"(lo));
    return r;
}
__device__ __forceinline__ void mma8(float (&c)[4], const unsigned (&a)[4],
                                     const unsigned (&b)[2]) {
    asm volatile(
        "mma.sync.aligned.m16n8k8.row.col.f32.tf32.tf32.f32 "
        "{%0,%1,%2,%3}, {%4,%5,%6,%7}, {%8,%9}, {%0,%1,%2,%3};"
        : "+f"(c[0]), "+f"(c[1]), "+f"(c[2]), "+f"(c[3])
        : "r"(a[0]), "r"(a[1]), "r"(a[2]), "r"(a[3]), "r"(b[0]), "r"(b[1]));
}
__device__ __forceinline__ void mma16f(float (&c)[4], const unsigned (&a)[4],
                                       const unsigned (&b)[2]) {
    asm volatile(
        "mma.sync.aligned.m16n8k16.row.col.f32.f16.f16.f32 "
        "{%0,%1,%2,%3}, {%4,%5,%6,%7}, {%8,%9}, {%0,%1,%2,%3};"
        : "+f"(c[0]), "+f"(c[1]), "+f"(c[2]), "+f"(c[3])
        : "r"(a[0]), "r"(a[1]), "r"(a[2]), "r"(a[3]), "r"(b[0]), "r"(b[1]));
}
// two-limb fp16 split of a float pair -> packed hi pair + lo pair
__device__ __forceinline__ void split2(float x0, float x1, unsigned &hp, unsigned &lp) {
    __half h0 = __float2half_rn(x0), h1 = __float2half_rn(x1);
    __half l0 = __float2half_rn(x0 - __half2float(h0));
    __half l1 = __float2half_rn(x1 - __half2float(h1));
    __half2 hh = __halves2half2(h0, h1);
    __half2 ll = __halves2half2(l0, l1);
    hp = *reinterpret_cast<unsigned*>(&hh);
    lp = *reinterpret_cast<unsigned*>(&ll);
}
__device__ __forceinline__ void cpa16(float* dst, const float* src, bool pred) {
    unsigned d = (unsigned)__cvta_generic_to_shared(dst);
    int sz = pred ? 16 : 0;
    asm volatile("cp.async.cg.shared.global [%0], [%1], 16, %2;"
                 :: "r"(d), "l"(src), "r"(sz));
}
#define CP_COMMIT() asm volatile("cp.async.commit_group;" ::: "memory")

// ---------------- prep: transpose to token-major concat + base canvas -----------
__global__ void prep_kernel(const float* __restrict__ f_ir,
                            const float* __restrict__ f_vis,
                            float* __restrict__ out)
{
    __shared__ float ti[32][33], tv[32][33];
    int b = blockIdx.z;
    int c0 = blockIdx.y * 32;
    int n0 = blockIdx.x * 32;
#pragma unroll
    for (int i = 0; i < 4; i++) {
        int c = c0 + threadIdx.y + i * 8;
        size_t off = ((size_t)b*256 + c)*NTOK + n0 + threadIdx.x;
        float vi = f_ir[off], vv = f_vis[off];
        ti[threadIdx.y + i*8][threadIdx.x] = vi;
        tv[threadIdx.y + i*8][threadIdx.x] = vv;
        out[off] = vi + vv;
    }
    __syncthreads();
#pragma unroll
    for (int i = 0; i < 4; i++) {
        int n = n0 + threadIdx.y + i * 8;
        size_t base = ((size_t)b*NTOK + n)*512;
        g_Xall[base + c0 + threadIdx.x]       = ti[threadIdx.x][threadIdx.y + i*8];
        g_Xall[base + 256 + c0 + threadIdx.x] = tv[threadIdx.x][threadIdx.y + i*8];
    }
}

// ---------------- agent GEMM: two-limb fp16, mma.m16n8k16 (R14-proven) ----------
__global__ void __launch_bounds__(256) agemm(const float* __restrict__ A,
                                             const float* __restrict__ W,
                                             const float* __restrict__ bias,
                                             float* __restrict__ C)
{
    int z = blockIdx.z;
    int row0 = blockIdx.x * 128;
    int n0 = blockIdx.y * 64;
    const float* Ab = A + (size_t)z * NTOK * AK;
    float*       Cb = C + (size_t)z * NTOK * AN;

    __shared__ unsigned As_hi[128*20], As_lo[128*20];
    __shared__ unsigned Ws_hi[64*20],  Ws_lo[64*20];

    int tid = threadIdx.x;
    int warp = tid >> 5, lane = tid & 31;
    int g = lane >> 2, tig = lane & 3;
    int wm = warp >> 1, wn = warp & 1;

    int arow = tid >> 1, ahalf = (tid & 1) * 16;
    int wrow = tid >> 2, wquart = (tid & 3) * 8;

    float acc[2][4][4];
#pragma unroll
    for (int mi = 0; mi < 2; mi++)
#pragma unroll
        for (int ni = 0; ni < 4; ni++)
#pragma unroll
            for (int q = 0; q < 4; q++) acc[mi][ni][q] = 0.f;

    for (int k0 = 0; k0 < AK; k0 += 32) {
        {
            const float* p = &Ab[(size_t)(row0 + arow) * AK + k0 + ahalf];
            unsigned hp[8], lp[8];
#pragma unroll
            for (int i = 0; i < 4; i++) {
                float4 v = *(const float4*)(p + 4*i);
                split2(v.x, v.y, hp[2*i],   lp[2*i]);
                split2(v.z, v.w, hp[2*i+1], lp[2*i+1]);
            }
            int off = arow*20 + (ahalf >> 1);
            *(uint4*)&As_hi[off]     = make_uint4(hp[0], hp[1], hp[2], hp[3]);
            *(uint4*)&As_hi[off + 4] = make_uint4(hp[4], hp[5], hp[6], hp[7]);
            *(uint4*)&As_lo[off]     = make_uint4(lp[0], lp[1], lp[2], lp[3]);
            *(uint4*)&As_lo[off + 4] = make_uint4(lp[4], lp[5], lp[6], lp[7]);
        }
        {
            const float* p = &W[(size_t)(n0 + wrow) * AK + k0 + wquart];
            float4 v0 = *(const float4*)(p);
            float4 v1 = *(const float4*)(p + 4);
            unsigned hp[4], lp[4];
            split2(v0.x, v0.y, hp[0], lp[0]);
            split2(v0.z, v0.w, hp[1], lp[1]);
            split2(v1.x, v1.y, hp[2], lp[2]);
            split2(v1.z, v1.w, hp[3], lp[3]);
            int off = wrow*20 + (wquart >> 1);
            *(uint4*)&Ws_hi[off] = make_uint4(hp[0], hp[1], hp[2], hp[3]);
            *(uint4*)&Ws_lo[off] = make_uint4(lp[0], lp[1], lp[2], lp[3]);
        }
        __syncthreads();

#pragma unroll
        for (int ks = 0; ks < 2; ks++) {
            int base = ks * 8;
            unsigned ah[2][4], al[2][4], bh[4][2], bl[4][2];
#pragma unroll
            for (int mi = 0; mi < 2; mi++) {
                int rb = wm*32 + mi*16;
                ah[mi][0] = As_hi[(rb + g    )*20 + base + tig];
                ah[mi][1] = As_hi[(rb + 8 + g)*20 + base + tig];
                ah[mi][2] = As_hi[(rb + g    )*20 + base + tig + 4];
                ah[mi][3] = As_hi[(rb + 8 + g)*20 + base + tig + 4];
                al[mi][0] = As_lo[(rb + g    )*20 + base + tig];
                al[mi][1] = As_lo[(rb + 8 + g)*20 + base + tig];
                al[mi][2] = As_lo[(rb + g    )*20 + base + tig + 4];
                al[mi][3] = As_lo[(rb + 8 + g)*20 + base + tig + 4];
            }
#pragma unroll
            for (int ni = 0; ni < 4; ni++) {
                int nb = wn*32 + ni*8;
                bh[ni][0] = Ws_hi[(nb + g)*20 + base + tig];
                bh[ni][1] = Ws_hi[(nb + g)*20 + base + tig + 4];
                bl[ni][0] = Ws_lo[(nb + g)*20 + base + tig];
                bl[ni][1] = Ws_lo[(nb + g)*20 + base + tig + 4];
            }
#pragma unroll
            for (int mi = 0; mi < 2; mi++)
#pragma unroll
                for (int ni = 0; ni < 4; ni++) {
                    mma16f(acc[mi][ni], ah[mi], bl[ni]);
                    mma16f(acc[mi][ni], al[mi], bh[ni]);
                    mma16f(acc[mi][ni], ah[mi], bh[ni]);
                }
        }
        __syncthreads();
    }

#pragma unroll
    for (int mi = 0; mi < 2; mi++) {
#pragma unroll
        for (int ni = 0; ni < 4; ni++) {
            int cb = n0 + wn*32 + ni*8 + 2*tig;
            float2 bb = *(const float2*)&bias[cb];
#pragma unroll
            for (int h = 0; h < 2; h++) {
                int row = row0 + wm*32 + mi*16 + g + h*8;
                float v0 = acc[mi][ni][h*2 + 0] + bb.x;
                float v1 = acc[mi][ni][h*2 + 1] + bb.y;
                v0 = v0 / (1.f + expf(-v0));
                v1 = v1 / (1.f + expf(-v1));
                *(float2*)&Cb[(size_t)row * AN + cb] = make_float2(v0, v1);
            }
        }
    }
}

// ---------------- mixer tf32 GEMM, cp.async double-buffer (R9-proven) -----------
template<int ACT, bool RES>
__global__ void __launch_bounds__(256) tgemm(
                      const float* __restrict__ A,
                      const float* __restrict__ W0, const float* __restrict__ W1,
                      const float* __restrict__ bias0, const float* __restrict__ bias1,
                      const float* __restrict__ R, float* __restrict__ C,
                      int K, int N)
{
    int z = blockIdx.z;
    int b = z & (NB - 1);
    int S = g_S[b];
    int row0 = blockIdx.x * 128;
    if (row0 >= S) return;
    const float* W    = (z < NB) ? W0 : W1;
    const float* bias = (z < NB) ? bias0 : bias1;
    int n0 = blockIdx.y * 64;
    const float* Ab = A + (size_t)z * NTOK * K;
    float*       Cb = C + (size_t)z * NTOK * N;
    const float* Rb = RES ? (R + (size_t)z * NTOK * N) : nullptr;

    extern __shared__ float sh[];
    float* Abuf[2] = { sh,            sh + 192*36 };
    float* Wbuf[2] = { sh + 128*36,   sh + 320*36 };

    int tid  = threadIdx.x;
    int warp = tid >> 5, lane = tid & 31;
    int g = lane >> 2, tig = lane & 3;
    int wm = warp >> 1, wn = warp & 1;

    int ar  = tid >> 3;
    int ac4 = (tid & 7) * 4;

    float acc[2][4][4];
#pragma unroll
    for (int mi = 0; mi < 2; mi++)
#pragma unroll
        for (int ni = 0; ni < 4; ni++)
#pragma unroll
            for (int q = 0; q < 4; q++) acc[mi][ni][q] = 0.f;

    const int NCH = K >> 5;

    auto issue = [&](int c, int bi) {
        int kc = c * 32;
#pragma unroll
        for (int it = 0; it < 4; it++) {
            int r = ar + it * 32;
            int row = row0 + r;
            bool ok = (row < S);
            cpa16(&Abuf[bi][r*36 + ac4], &Ab[(size_t)(ok ? row : 0) * K + kc + ac4], ok);
        }
#pragma unroll
        for (int it = 0; it < 2; it++) {
            int r = ar + it * 32;
            cpa16(&Wbuf[bi][r*36 + ac4], &W[(size_t)(n0 + r) * K + kc + ac4], true);
        }
    };

    issue(0, 0);
    CP_COMMIT();

    for (int c = 0; c < NCH; c++) {
        int cur = c & 1;
        if (c + 1 < NCH) { issue(c + 1, cur ^ 1); CP_COMMIT(); }
        if (c + 1 < NCH) asm volatile("cp.async.wait_group 1;" ::: "memory");
        else             asm volatile("cp.async.wait_group 0;" ::: "memory");
        __syncthreads();

        const float* Asb = Abuf[cur];
        const float* Wsb = Wbuf[cur];
#pragma unroll
        for (int ks = 0; ks < 4; ks++) {
            int base = ks * 8;
            unsigned a_hi[2][4], b_hi[4][2];
#pragma unroll
            for (int mi = 0; mi < 2; mi++) {
                int rb = wm*32 + mi*16;
                a_hi[mi][0] = f2tf(Asb[(rb + g    )*36 + base + tig]);
                a_hi[mi][1] = f2tf(Asb[(rb + 8 + g)*36 + base + tig]);
                a_hi[mi][2] = f2tf(Asb[(rb + g    )*36 + base + tig + 4]);
                a_hi[mi][3] = f2tf(Asb[(rb + 8 + g)*36 + base + tig + 4]);
            }
#pragma unroll
            for (int ni = 0; ni < 4; ni++) {
                int nb = wn*32 + ni*8;
                b_hi[ni][0] = f2tf(Wsb[(nb + g)*36 + base + tig]);
                b_hi[ni][1] = f2tf(Wsb[(nb + g)*36 + base + tig + 4]);
            }
#pragma unroll
            for (int mi = 0; mi < 2; mi++)
#pragma unroll
                for (int ni = 0; ni < 4; ni++)
                    mma8(acc[mi][ni], a_hi[mi], b_hi[ni]);
        }
        __syncthreads();
    }

#pragma unroll
    for (int mi = 0; mi < 2; mi++) {
#pragma unroll
        for (int ni = 0; ni < 4; ni++) {
            int cb = n0 + wn*32 + ni*8 + 2*tig;
            float2 bb = *(const float2*)&bias[cb];
#pragma unroll
            for (int h = 0; h < 2; h++) {
                int row = row0 + wm*32 + mi*16 + g + h*8;
                if (row >= S) continue;
                float v0 = acc[mi][ni][h*2 + 0] + bb.x;
                float v1 = acc[mi][ni][h*2 + 1] + bb.y;
                if (ACT == 1) {
                    v0 = 0.5f * v0 * (1.f + erff(v0 * 0.70710678118654752f));
                    v1 = 0.5f * v1 * (1.f + erff(v1 * 0.70710678118654752f));
                }
                if (RES) {
                    float2 rr = *(const float2*)&Rb[(size_t)row * N + cb];
                    v0 += rr.x; v1 += rr.y;
                }
                *(float2*)&Cb[(size_t)row * N + cb] = make_float2(v0, v1);
            }
        }
    }
}

// ---------------- logits: lf[p] = h1[p]·aw2 + ab2 (warp per pixel) --------------
__global__ void logits_kernel(const float* __restrict__ aw2,
                              const float* __restrict__ ab2)
{
    int p = blockIdx.x * 8 + (threadIdx.x >> 5);
    int lane = threadIdx.x & 31;
    const float* h = g_h1 + (size_t)p * AGH;
    float s = 0.f;
#pragma unroll
    for (int j = 0; j < 16; j++) s += h[lane + 32*j] * aw2[lane + 32*j];
#pragma unroll
    for (int o = 16; o > 0; o >>= 1) s += __shfl_xor_sync(0xffffffffu, s, o);
    if (lane == 0) g_lf[p] = s + ab2[0];
}

// ---------------- selection + top-64 fallback + compaction ----------------------
__global__ void select_kernel()
{
    __shared__ float vals[NTOK];
    __shared__ int   sels[NTOK];
    __shared__ int   wtot[8];
    __shared__ int   scount;
    __shared__ float rv[256];
    __shared__ int   ri[256];
    int b = blockIdx.x, tid = threadIdx.x;
    int lane = tid & 31, w = tid >> 5;

    int localc = 0;
    for (int n = tid; n < NTOK; n += 256) {
        float v = g_lf[b*NTOK + n];
        vals[n] = v;
        int s = (v > 0.f) ? 1 : 0;
        sels[n] = s;
        g_maskf[b*NTOK + n] = s ? 1.f : 0.f;
        localc += s;
    }
    {
        int c = localc;
#pragma unroll
        for (int o = 16; o > 0; o >>= 1) c += __shfl_xor_sync(0xffffffffu, c, o);
        if (lane == 0) wtot[w] = c;
        __syncthreads();
        if (tid == 0) { int t = 0; for (int i = 0; i < 8; i++) t += wtot[i]; scount = t; }
        __syncthreads();
    }
    int count = scount;

    if (count < 64) {
        for (int n = tid; n < NTOK; n += 256) sels[n] = 0;
        __syncthreads();
        for (int iter = 0; iter < 64; iter++) {
            float bv = -1e38f; int bi = NTOK;
            for (int n = tid; n < NTOK; n += 256)
                if (!sels[n] && vals[n] > bv) { bv = vals[n]; bi = n; }
            rv[tid] = bv; ri[tid] = bi;
            __syncthreads();
            for (int o = 128; o > 0; o >>= 1) {
                if (tid < o) {
                    if (rv[tid+o] > rv[tid] ||
                        (rv[tid+o] == rv[tid] && ri[tid+o] < ri[tid])) {
                        rv[tid] = rv[tid+o]; ri[tid] = ri[tid+o];
                    }
                }
                __syncthreads();
            }
            if (tid == 0) sels[ri[0]] = 1;
            __syncthreads();
        }
    }

    int base = tid * 9;
    int lc = 0;
#pragma unroll
    for (int k = 0; k < 9; k++) lc += sels[base + k];
    int inc = lc;
#pragma unroll
    for (int o = 1; o < 32; o <<= 1) {
        int v = __shfl_up_sync(0xffffffffu, inc, o);
        if (lane >= o) inc += v;
    }
    if (lane == 31) wtot[w] = inc;
    __syncthreads();
    if (tid < 8) {
        int v = wtot[tid];
#pragma unroll
        for (int o = 1; o < 8; o <<= 1) {
            int u = __shfl_up_sync(0xffu, v, o);
            if (tid >= o) v += u;
        }
        wtot[tid] = v;
    }
    __syncthreads();
    int pos = inc - lc + (w ? wtot[w-1] : 0);
    if (tid == 0) g_S[b] = wtot[7];
#pragma unroll
    for (int k = 0; k < 9; k++)
        if (sels[base + k]) g_idx[b*NTOK + pos++] = base + k;
}

// ---------------- gather compacted tokens (both modules) ------------------------
__global__ void gather_kernel()
{
    int b = blockIdx.y, s = blockIdx.x;
    if (s >= g_S[b]) return;
    int n = g_idx[b*NTOK + s];
    int c = threadIdx.x;
    const float* src = g_Xall + ((size_t)b*NTOK + n)*512;
    g_X[((size_t)b*NTOK + s)*DIM + c]        = src[c];
    g_X[((size_t)(NB + b)*NTOK + s)*DIM + c] = src[256 + c];
}

// ---------------- LayerNorm (warp per token) ------------------------------------
__global__ void ln_kernel(const float* __restrict__ X,
                          const float* __restrict__ g0, const float* __restrict__ b0_,
                          const float* __restrict__ g1, const float* __restrict__ b1_,
                          float* __restrict__ O)
{
    int z = blockIdx.y;
    int b = z & (NB - 1);
    int t = blockIdx.x * 8 + (threadIdx.x >> 5);
    if (t >= g_S[b]) return;
    const float* gg = (z < NB) ? g0 : g1;
    const float* bb = (z < NB) ? b0_ : b1_;
    int lane = threadIdx.x & 31;
    const float* x = X + ((size_t)z*NTOK + t)*DIM;
    float v[8];
    float s = 0.f;
#pragma unroll
    for (int j = 0; j < 8; j++) { v[j] = x[lane + 32*j]; s += v[j]; }
#pragma unroll
    for (int o = 16; o > 0; o >>= 1) s += __shfl_xor_sync(0xffffffffu, s, o);
    float mean = s * (1.f/256.f);
    float vs = 0.f;
#pragma unroll
    for (int j = 0; j < 8; j++) { float d = v[j] - mean; vs += d*d; }
#pragma unroll
    for (int o = 16; o > 0; o >>= 1) vs += __shfl_xor_sync(0xffffffffu, vs, o);
    float rstd = rsqrtf(vs * (1.f/256.f) + 1e-5f);
    float* o = O + ((size_t)z*NTOK + t)*DIM;
#pragma unroll
    for (int j = 0; j < 8; j++) {
        int c = lane + 32*j;
        o[c] = (v[j] - mean) * rstd * gg[c] + bb[c];
    }
}

// ---------------- flash attention, FA2 layout: Q-tile 128, warp m16xn64 ---------
// QK in tf32; softmax warp-local (quad shfl); P packed fp16 IN REGISTERS
// (S-accum fragment layout == PV A-operand layout); V fp16 key-pairs in smem.
// 2 syncs per 64-key tile; no score smem buffer.
__global__ void __launch_bounds__(256) flash_kernel()
{
    extern __shared__ unsigned fsm[];
    unsigned* Qs = fsm;               // [128][68] tf32
    unsigned* Ks = fsm + 128*68;      // [64][68]  tf32
    unsigned* Vp = fsm + 192*68;      // [32 key-pairs][72] fp16x2 (banks 8t+g distinct)

    int z = blockIdx.z;
    int b = z & (NB - 1);
    int h = blockIdx.y;
    int S = g_S[b];
    int qb = blockIdx.x * 128;
    if (qb >= S) return;
    int tid = threadIdx.x;
    int w = tid >> 5, lane = tid & 31;
    int g = lane >> 2, tig = lane & 3;
    const float* qkvb = g_qkv + (size_t)z * NTOK * 768;

    // load Q tile 128x64 (tf32)
#pragma unroll
    for (int it = 0; it < 8; it++) {
        int lin = tid + it * 256;
        int r = lin >> 4, c4 = (lin & 15) * 4;
        int t = qb + r;
        float4 v = make_float4(0.f, 0.f, 0.f, 0.f);
        if (t < S) v = *(const float4*)&qkvb[(size_t)t*768 + h*64 + c4];
        uint4 hv; hv.x = f2tf(v.x); hv.y = f2tf(v.y); hv.z = f2tf(v.z); hv.w = f2tf(v.w);
        *(uint4*)&Qs[r*68 + c4] = hv;
    }

    float m0 = -1e30f, l0 = 0.f, m1 = -1e30f, l1 = 0.f;
    float oacc[8][4];
#pragma unroll
    for (int dt = 0; dt < 8; dt++)
#pragma unroll
        for (int q = 0; q < 4; q++) oacc[dt][q] = 0.f;

    for (int kb = 0; kb < S; kb += 64) {
        __syncthreads();   // protect prior iteration's K/V reads (and Q writes on iter 0)
        // load K tile (tf32)
#pragma unroll
        for (int it = 0; it < 4; it++) {
            int lin = tid + it * 256;
            int r = lin >> 4, c4 = (lin & 15) * 4;
            int t = kb + r;
            float4 v = make_float4(0.f, 0.f, 0.f, 0.f);
            if (t < S) v = *(const float4*)&qkvb[(size_t)t*768 + 256 + h*64 + c4];
            uint4 hv; hv.x = f2tf(v.x); hv.y = f2tf(v.y); hv.z = f2tf(v.z); hv.w = f2tf(v.w);
            *(uint4*)&Ks[r*68 + c4] = hv;
        }
        // load V as fp16 key-pairs: Vp[pi][d] = half2(V[2pi][d], V[2pi+1][d])
#pragma unroll
        for (int it = 0; it < 8; it++) {
            int lin = tid + it * 256;
            int pi = lin >> 6, d = lin & 63;
            int t0 = kb + 2*pi, t1 = t0 + 1;
            float v0 = (t0 < S) ? qkvb[(size_t)t0*768 + 512 + h*64 + d] : 0.f;
            float v1 = (t1 < S) ? qkvb[(size_t)t1*768 + 512 + h*64 + d] : 0.f;
            Vp[pi*72 + d] = pack_f16(v0, v1);
        }
        __syncthreads();

        // S = Q K^T : warp tile m16 (rows w*16..) x n64 (all keys)
        float sacc[8][4];
#pragma unroll
        for (int ni = 0; ni < 8; ni++)
#pragma unroll
            for (int q = 0; q < 4; q++) sacc[ni][q] = 0.f;
#pragma unroll
        for (int ks = 0; ks < 8; ks++) {
            int base = ks * 8;
            unsigned a[4];
            int rb = w * 16;
            a[0] = Qs[(rb + g    )*68 + base + tig];
            a[1] = Qs[(rb + 8 + g)*68 + base + tig];
            a[2] = Qs[(rb + g    )*68 + base + tig + 4];
            a[3] = Qs[(rb + 8 + g)*68 + base + tig + 4];
#pragma unroll
            for (int ni = 0; ni < 8; ni++) {
                unsigned bf[2];
                bf[0] = Ks[(ni*8 + g)*68 + base + tig];
                bf[1] = Ks[(ni*8 + g)*68 + base + tig + 4];
                mma8(sacc[ni], a, bf);
            }
        }
        // scale + mask
#pragma unroll
        for (int ni = 0; ni < 8; ni++) {
            int key = kb + ni*8 + 2*tig;
            sacc[ni][0] *= 0.125f; sacc[ni][1] *= 0.125f;
            sacc[ni][2] *= 0.125f; sacc[ni][3] *= 0.125f;
            if (key     >= S) { sacc[ni][0] = -1e30f; sacc[ni][2] = -1e30f; }
            if (key + 1 >= S) { sacc[ni][1] = -1e30f; sacc[ni][3] = -1e30f; }
        }
        // warp-local online softmax (rows g and g+8; quad shfl over tig)
        {
            float rm0 = -1e30f, rm1 = -1e30f;
#pragma unroll
            for (int ni = 0; ni < 8; ni++) {
                rm0 = fmaxf(rm0, fmaxf(sacc[ni][0], sacc[ni][1]));
                rm1 = fmaxf(rm1, fmaxf(sacc[ni][2], sacc[ni][3]));
            }
            rm0 = fmaxf(rm0, __shfl_xor_sync(0xffffffffu, rm0, 1));
            rm0 = fmaxf(rm0, __shfl_xor_sync(0xffffffffu, rm0, 2));
            rm1 = fmaxf(rm1, __shfl_xor_sync(0xffffffffu, rm1, 1));
            rm1 = fmaxf(rm1, __shfl_xor_sync(0xffffffffu, rm1, 2));
            float mn0 = fmaxf(m0, rm0), mn1 = fmaxf(m1, rm1);
            float al0 = __expf(m0 - mn0), al1 = __expf(m1 - mn1);
            m0 = mn0; m1 = mn1;
            float rs0 = 0.f, rs1 = 0.f;
#pragma unroll
            for (int ni = 0; ni < 8; ni++) {
                sacc[ni][0] = __expf(sacc[ni][0] - mn0);
                sacc[ni][1] = __expf(sacc[ni][1] - mn0);
                sacc[ni][2] = __expf(sacc[ni][2] - mn1);
                sacc[ni][3] = __expf(sacc[ni][3] - mn1);
                rs0 += sacc[ni][0] + sacc[ni][1];
                rs1 += sacc[ni][2] + sacc[ni][3];
            }
            rs0 += __shfl_xor_sync(0xffffffffu, rs0, 1);
            rs0 += __shfl_xor_sync(0xffffffffu, rs0, 2);
            rs1 += __shfl_xor_sync(0xffffffffu, rs1, 1);
            rs1 += __shfl_xor_sync(0xffffffffu, rs1, 2);
            l0 = l0 * al0 + rs0;
            l1 = l1 * al1 + rs1;
#pragma unroll
            for (int dt = 0; dt < 8; dt++) {
                oacc[dt][0] *= al0; oacc[dt][1] *= al0;
                oacc[dt][2] *= al1; oacc[dt][3] *= al1;
            }
        }
        // pack P to fp16 A-fragments in registers (no smem roundtrip)
        unsigned pv[4][4];
#pragma unroll
        for (int s = 0; s < 4; s++) {
            pv[s][0] = pack_f16(sacc[2*s][0],   sacc[2*s][1]);
            pv[s][1] = pack_f16(sacc[2*s][2],   sacc[2*s][3]);
            pv[s][2] = pack_f16(sacc[2*s+1][0], sacc[2*s+1][1]);
            pv[s][3] = pack_f16(sacc[2*s+1][2], sacc[2*s+1][3]);
        }
        // O += P V : 4 k16 slabs x 8 d-tiles
#pragma unroll
        for (int s = 0; s < 4; s++) {
#pragma unroll
            for (int dt = 0; dt < 8; dt++) {
                unsigned bf[2];
                bf[0] = Vp[(8*s + tig    )*72 + dt*8 + g];
                bf[1] = Vp[(8*s + 4 + tig)*72 + dt*8 + g];
                mma16f(oacc[dt], pv[s], bf);
            }
        }
    }

    // normalize + store
    {
        float il0 = 1.f / l0, il1 = 1.f / l1;
        int t0 = qb + w*16 + g, t1 = t0 + 8;
        float* ab = g_attn + (size_t)z * NTOK * DIM;
#pragma unroll
        for (int dt = 0; dt < 8; dt++) {
            int d = h*64 + dt*8 + 2*tig;
            if (t0 < S)
                *(float2*)&ab[(size_t)t0*DIM + d] = make_float2(oacc[dt][0]*il0, oacc[dt][1]*il0);
            if (t1 < S)
                *(float2*)&ab[(size_t)t1*DIM + d] = make_float2(oacc[dt][2]*il1, oacc[dt][3]*il1);
        }
    }
}

// ---------------- final scatter -------------------------------------------------
__global__ void scatter_kernel(float* __restrict__ out)
{
    int b = blockIdx.y, s = blockIdx.x;
    if (s >= g_S[b]) return;
    int n = g_idx[b*NTOK + s];
    int c = threadIdx.x;
    float v = (g_mix[((size_t)b*NTOK + s)*DIM + c] +
               g_mix[((size_t)(NB + b)*NTOK + s)*DIM + c]) * g_maskf[b*NTOK + n];
    out[((size_t)b*DIM + c)*NTOK + n] = v;
}

// ---------------- host ----------------------------------------------------------
#define GETSYM(ptr, sym) cudaGetSymbolAddress((void**)&(ptr), sym)

extern "C" void kernel_launch(void* const* d_in, const int* in_sizes, int n_in,
                              void* d_out, int out_size)
{
    const float* f_ir  = (const float*)d_in[0];
    const float* f_vis = (const float*)d_in[1];
    const float* aw1   = (const float*)d_in[2];
    const float* ab1   = (const float*)d_in[3];
    const float* aw2   = (const float*)d_in[4];
    const float* ab2   = (const float*)d_in[5];
    const float* P[20];
    for (int i = 0; i < 20; i++) P[i] = (const float*)d_in[6 + i];
    float* out = (float*)d_out;

    float *p_Xall, *p_h1, *p_X, *p_xn, *p_qkv, *p_attn, *p_x1, *p_hff, *p_mix;
    GETSYM(p_Xall, g_Xall); GETSYM(p_h1, g_h1); GETSYM(p_X, g_X);
    GETSYM(p_xn, g_xn);     GETSYM(p_qkv, g_qkv); GETSYM(p_attn, g_attn);
    GETSYM(p_x1, g_x1);     GETSYM(p_hff, g_hff); GETSYM(p_mix, g_mix);

    const int SMG = 2*192*36*4;              // 55296 B : mixer double buffer
    const int SMF = (192*68 + 32*72) * 4;    // 61440 B : flash (Q+K tf32, V fp16 pairs)

    cudaFuncSetAttribute(tgemm<0,false>, cudaFuncAttributeMaxDynamicSharedMemorySize, SMG);
    cudaFuncSetAttribute(tgemm<0,true >, cudaFuncAttributeMaxDynamicSharedMemorySize, SMG);
    cudaFuncSetAttribute(tgemm<1,false>, cudaFuncAttributeMaxDynamicSharedMemorySize, SMG);
    cudaFuncSetAttribute(flash_kernel, cudaFuncAttributeMaxDynamicSharedMemorySize, SMF);

    prep_kernel<<<dim3(72, 8, NB), dim3(32, 8)>>>(f_ir, f_vis, out);
    agemm<<<dim3(18, 8, NB), 256>>>(p_Xall, aw1, ab1, p_h1);
    logits_kernel<<<1152, 256>>>(aw2, ab2);
    select_kernel<<<NB, 256>>>();
    gather_kernel<<<dim3(NTOK, NB), 256>>>();

    ln_kernel<<<dim3(288, 8), 256>>>(p_X, P[0], P[1], P[10], P[11], p_xn);
    tgemm<0,false><<<dim3(18, 12, 8), 256, SMG>>>(
        p_xn, P[2], P[12], P[3], P[13], nullptr, p_qkv, 256, 768);
    flash_kernel<<<dim3(18, 4, 8), 256, SMF>>>();
    tgemm<0,true><<<dim3(18, 4, 8), 256, SMG>>>(
        p_attn, P[4], P[14], P[5], P[15], p_X, p_x1, 256, 256);
    ln_kernel<<<dim3(288, 8), 256>>>(p_x1, P[0], P[1], P[10], P[11], p_xn);
    tgemm<1,false><<<dim3(18, 16, 8), 256, SMG>>>(
        p_xn, P[6], P[16], P[7], P[17], nullptr, p_hff, 256, 1024);
    tgemm<0,true><<<dim3(18, 4, 8), 256, SMG>>>(
        p_hff, P[8], P[18], P[9], P[19], p_x1, p_mix, 1024, 256);

    scatter_kernel<<<dim3(NTOK, NB), 256>>>(out);
}